// round 12
// baseline (speedup 1.0000x reference)
#include <cuda_runtime.h>
#include <cstddef>
#include <cstdint>

// ---------------------------------------------------------------------------
// Sparse 3D UNet forward.  tf32 mma.sync.m16n8k8 sparse-conv GEMM.
// R11: 3-deep cp.async ring pipeline with ONE __syncthreads per stage
// (wait -> barrier -> issue s+2 -> compute s), batched weight packing.
// ---------------------------------------------------------------------------

__device__ float g_pool[224u * 1024u * 1024u];   // 896 MB scratch (static: legal)

__device__ __forceinline__ void cp_async16(uint32_t dst, const void* src, int nbytes) {
    asm volatile("cp.async.cg.shared.global [%0], [%1], 16, %2;"
                 :: "r"(dst), "l"(src), "r"(nbytes));
}
__device__ __forceinline__ void cp_commit() {
    asm volatile("cp.async.commit_group;");
}
template <int NG> __device__ __forceinline__ void cp_wait() {
    asm volatile("cp.async.wait_group %0;" :: "n"(NG));
}
__device__ __forceinline__ uint32_t tf32(float x) {
    uint32_t r; asm("cvt.rna.tf32.f32 %0, %1;" : "=r"(r) : "f"(x)); return r;
}
__device__ __forceinline__ void mma_tf32(float c[4], uint32_t a0, uint32_t a1,
                                         uint32_t a2, uint32_t a3,
                                         uint32_t b0, uint32_t b1) {
    asm volatile(
        "mma.sync.aligned.m16n8k8.row.col.f32.tf32.tf32.f32 "
        "{%0,%1,%2,%3},{%4,%5,%6,%7},{%8,%9},{%0,%1,%2,%3};"
        : "+f"(c[0]), "+f"(c[1]), "+f"(c[2]), "+f"(c[3])
        : "r"(a0), "r"(a1), "r"(a2), "r"(a3), "r"(b0), "r"(b1));
}

__global__ void cvt_tf32_kernel(const float* __restrict__ in,
                                float* __restrict__ out, int n) {
    for (int i = blockIdx.x * blockDim.x + threadIdx.x; i < n;
         i += gridDim.x * blockDim.x)
        out[i] = __uint_as_float(tf32(in[i]));
}

template <int CIN, int COUT>
struct SpCfg {
    static constexpr int BM  = 128;
    static constexpr int NB  = 3;                       // pipeline depth
    static constexpr int CK  = (CIN < 32) ? CIN : 32;
    static constexpr int CK8 = (CK < 8) ? 8 : CK;
    static constexpr int NCH = CIN / CK;
    static constexpr int SP  = CK8 + 4;
    static constexpr int VR  = CK / 4;
    static constexpr int NT  = COUT / 8;
    static constexpr int KS  = CK8 / 8;
    static constexpr int P   = 2 * NT;
    static constexpr int PS  = P + 4;
    static constexpr int WSTG = KS * 32 * P;
    static constexpr int WSMS = KS * 32 * PS;
    static constexpr int SMEM_BYTES =
        (NB * BM * SP + NB * WSMS) * 4 + 27 * BM * 4 + 64 * 4;
    static constexpr int PACKED_PER_LAYER = 27 * NCH * WSTG;
};

// Pack ALL layers of one family in one launch.  Layout per layer:
// [k][ch][k8][lane][p],  p = 2t+j,
//   value = W[l][k][ch*CK + k8*8 + (lane&3) + 4j][t*8 + (lane>>2)]  (tf32)
template <int CIN, int COUT>
__global__ void pack_w_kernel(const float* __restrict__ W, float* __restrict__ Wp,
                              int layers) {
    using C = SpCfg<CIN, COUT>;
    const int per = C::PACKED_PER_LAYER;
    const int total = layers * per;
    const size_t src_per = 27u * CIN * COUT;
    for (int o = blockIdx.x * blockDim.x + threadIdx.x; o < total;
         o += gridDim.x * blockDim.x) {
        int l = o / per;
        int q = o - l * per;
        int p = q % C::P;
        int rest = q / C::P;
        int ln = rest % 32; rest /= 32;
        int k8 = rest % C::KS; rest /= C::KS;
        int ch = rest % C::NCH;
        int k  = rest / C::NCH;
        int kq = ln & 3, nq = ln >> 2;
        int t = p >> 1, j = p & 1;
        int rk  = k8 * 8 + kq + 4 * j;
        int col = t * 8 + nq;
        float v = 0.f;
        if (rk < C::CK)
            v = W[(size_t)l * src_per +
                  ((size_t)k * CIN + ch * C::CK + rk) * COUT + col];
        Wp[o] = __uint_as_float(tf32(v));
    }
}

template <int CIN, int COUT>
__global__ void __launch_bounds__(256)
spconv_mma(const float* __restrict__ feat, int ldf,   // tf32 input
           const int* __restrict__ nbr,
           const float* __restrict__ Wp,              // packed tf32 weights
           const float* __restrict__ sb,
           const float* __restrict__ resid, int ldr,
           const float* __restrict__ red,   int ldred,
           float* __restrict__ out, int ldo,
           float* __restrict__ outs,                  // tf32 shadow (or null)
           int N)
{
    using C = SpCfg<CIN, COUT>;
    constexpr int BM = C::BM, NB = C::NB, CK = C::CK, CK8 = C::CK8;
    constexpr int NCH = C::NCH, SP = C::SP, VR = C::VR, NT = C::NT, KS = C::KS;
    constexpr int P = C::P, PS = C::PS, WSTG = C::WSTG, WSMS = C::WSMS;

    extern __shared__ float smem[];
    float* sfeat = smem;                              // [NB][BM*SP]
    float* sW    = smem + NB * BM * SP;               // [NB][WSMS]
    int*   snbr  = (int*)(sW + NB * WSMS);            // [27*BM]
    int*   kmeta = snbr + 27 * BM;
    int*   khit  = kmeta;
    int*   klist = kmeta + 27;
    int*   knp   = kmeta + 54;

    const uint32_t sfeat_sa = (uint32_t)__cvta_generic_to_shared(sfeat);
    const uint32_t sW_sa    = (uint32_t)__cvta_generic_to_shared(sW);

    const int tid  = threadIdx.x;
    const int lane = tid & 31;
    const int wid  = tid >> 5;
    const int row0 = blockIdx.x * BM;

    if (CK8 != CK) {   // zero feature pad region once (CIN=4 layer)
        for (int u = tid; u < NB * BM * SP; u += 256) smem[u] = 0.f;
    }

    // Stage neighbor indices
    for (int e = tid; e < BM * 27; e += 256) {
        int r = e / 27, k = e - r * 27;
        int g = row0 + r;
        snbr[k * BM + r] = (g < N) ? nbr[(size_t)g * 27 + k] : -1;
    }
    __syncthreads();
    if (tid < 27) {
        int h = 0;
        for (int r = 0; r < BM && !h; ++r) h = (snbr[tid * BM + r] >= 0);
        khit[tid] = h;
    }
    __syncthreads();
    if (tid == 0) {
        int n = 0;
        for (int k = 0; k < 27; ++k) if (khit[k]) klist[n++] = k;
        *knp = n;
    }
    __syncthreads();
    const int NS = (*knp) * NCH;

    float acc[NT][4];
#pragma unroll
    for (int t = 0; t < NT; ++t)
#pragma unroll
        for (int j = 0; j < 4; ++j) acc[t][j] = 0.f;

    auto stage = [&](int s) {
        const int k  = klist[s / NCH];
        const int ch = s - (s / NCH) * NCH;
        const int kb = s % NB;
        const uint32_t fb = sfeat_sa + (uint32_t)(kb * BM * SP) * 4u;
        for (int u = tid; u < BM * VR; u += 256) {
            int r = u / VR, v = u - r * VR;
            int idx = snbr[k * BM + r];
            const float* g = feat + (size_t)(idx < 0 ? 0 : idx) * ldf
                           + ch * CK + v * 4;
            cp_async16(fb + (uint32_t)(r * SP + v * 4) * 4u, g, idx < 0 ? 0 : 16);
        }
        const float* wg = Wp + (size_t)(k * NCH + ch) * WSTG;
        const uint32_t wb = sW_sa + (uint32_t)(kb * WSMS) * 4u;
        for (int u = tid; u < WSTG / 4; u += 256) {
            int ln8 = u / (P / 4);
            int c   = u - ln8 * (P / 4);
            cp_async16(wb + (uint32_t)(ln8 * PS + 4 * c) * 4u,
                       wg + ln8 * P + 4 * c, 16);
        }
    };

    const int mrow = wid * 16 + (lane >> 2);
    const int kq   = lane & 3;

    if (NS > 0) {
        stage(0); cp_commit();
        if (NS > 1) { stage(1); cp_commit(); }

        for (int s = 0; s < NS; ++s) {
            if (s + 1 < NS) cp_wait<1>(); else cp_wait<0>();
            __syncthreads();                     // compute(s-1) done by ALL
            if (s + 2 < NS) { stage(s + 2); cp_commit(); }

            const int kb = s % NB;
            const float* fb = sfeat + kb * BM * SP;
            const float* wb = sW    + kb * WSMS;
#pragma unroll
            for (int k8 = 0; k8 < KS; ++k8) {
                const int kc = k8 * 8;
                const float* fr0 = fb + mrow * SP + kc + kq;
                const float* fr1 = fr0 + 8 * SP;
                uint32_t a0 = __float_as_uint(fr0[0]);
                uint32_t a1 = __float_as_uint(fr1[0]);
                uint32_t a2 = __float_as_uint(fr0[4]);
                uint32_t a3 = __float_as_uint(fr1[4]);
                const float* wrow = wb + (k8 * 32 + lane) * PS;
                float barr[P];
#pragma unroll
                for (int c = 0; c < P / 4; ++c)
                    *(float4*)(barr + 4 * c) = *(const float4*)(wrow + 4 * c);
#pragma unroll
                for (int t = 0; t < NT; ++t)
                    mma_tf32(acc[t], a0, a1, a2, a3,
                             __float_as_uint(barr[2 * t]),
                             __float_as_uint(barr[2 * t + 1]));
            }
            // no trailing barrier: next iteration's barrier covers the hazard
        }
    }

    // -------- epilogue --------
    const int r0 = row0 + mrow;
#pragma unroll
    for (int t = 0; t < NT; ++t) {
        const int col = t * 8 + 2 * kq;
        const float s0 = sb[col],        s1 = sb[col + 1];
        const float b0 = sb[COUT + col], b1 = sb[COUT + col + 1];
#pragma unroll
        for (int h = 0; h < 2; ++h) {
            const int r = r0 + 8 * h;
            if (r >= N) continue;
            float v0 = acc[t][2 * h]     * s0 + b0;
            float v1 = acc[t][2 * h + 1] * s1 + b1;
            if (resid) {
                float2 rr = *(const float2*)(resid + (size_t)r * ldr + col);
                v0 += rr.x; v1 += rr.y;
            }
            v0 = fmaxf(v0, 0.f);
            v1 = fmaxf(v1, 0.f);
            if (red) {
                float4 ra = *(const float4*)(red + (size_t)r * ldred + 2 * col);
                v0 += ra.x + ra.y;
                v1 += ra.z + ra.w;
            }
            *(float2*)(out + (size_t)r * ldo + col) = make_float2(v0, v1);
            if (outs)
                *(float2*)(outs + (size_t)r * ldo + col) =
                    make_float2(__uint_as_float(tf32(v0)), __uint_as_float(tf32(v1)));
        }
    }
}

template <int CIN, int COUT>
static void conv_launch(const float* feat, int ldf, const int* nbr,
                        const float* Wp, const float* sb,
                        const float* resid, int ldr,
                        const float* red, int ldred,
                        float* out, int ldo, float* outs, int N)
{
    constexpr int SM = SpCfg<CIN, COUT>::SMEM_BYTES;
    cudaFuncSetAttribute(spconv_mma<CIN, COUT>,
                         cudaFuncAttributeMaxDynamicSharedMemorySize, SM);
    const int grid = (N + 127) / 128;
    spconv_mma<CIN, COUT><<<grid, 256, SM>>>(
        feat, ldf, nbr, Wp, sb, resid, ldr, red, ldred, out, ldo, outs, N);
}

template <int CIN, int COUT>
static void pack_launch(const float* W, float* Wp, int layers)
{
    constexpr int per = SpCfg<CIN, COUT>::PACKED_PER_LAYER;
    const int total = layers * per;
    pack_w_kernel<CIN, COUT><<<(total + 255) / 256, 256>>>(W, Wp, layers);
}

extern "C" void kernel_launch(void* const* d_in, const int* in_sizes, int n_in,
                              void* d_out, int out_size)
{
    const float* voxel  = (const float*)d_in[0];
    const float* Win    = (const float*)d_in[1];
    const float* W32    = (const float*)d_in[2];
    const float* W64    = (const float*)d_in[3];
    const float* Wd3    = (const float*)d_in[4];
    const float* W6432  = (const float*)d_in[5];
    const float* W12864 = (const float*)d_in[6];
    const float* bn32   = (const float*)d_in[7];
    const float* bn64   = (const float*)d_in[8];
    const int* nbr1  = (const int*)d_in[9];
    const int* nbr2  = (const int*)d_in[10];
    const int* nbr3  = (const int*)d_in[11];
    const int* nbr4  = (const int*)d_in[12];
    const int* nbrd2 = (const int*)d_in[13];
    const int* nbrd3 = (const int*)d_in[14];
    const int* nbrd4 = (const int*)d_in[15];
    const int* nbri4 = (const int*)d_in[16];
    const int* nbri3 = (const int*)d_in[17];
    const int* nbri2 = (const int*)d_in[18];

    const int N1 = in_sizes[9]  / 27;
    const int N2 = in_sizes[10] / 27;
    const int N3 = in_sizes[11] / 27;
    const int N4 = in_sizes[12] / 27;

    float* pool = nullptr;
    cudaGetSymbolAddress((void**)&pool, g_pool);

    size_t o = 0;
    auto take = [&](size_t n) { size_t r = o; o += (n + 255) & ~(size_t)255; return r; };

    constexpr int Pin    = SpCfg<4, 32>::PACKED_PER_LAYER;
    constexpr int P32    = SpCfg<32, 32>::PACKED_PER_LAYER;
    constexpr int P64    = SpCfg<64, 64>::PACKED_PER_LAYER;
    constexpr int Pd3    = SpCfg<32, 64>::PACKED_PER_LAYER;
    constexpr int P6432  = SpCfg<64, 32>::PACKED_PER_LAYER;
    constexpr int P12864 = SpCfg<128, 64>::PACKED_PER_LAYER;
    float* pWin    = pool + take(Pin);
    float* pW32    = pool + take((size_t)10 * P32);
    float* pW64    = pool + take((size_t)10 * P64);
    float* pWd3    = pool + take(Pd3);
    float* pW6432  = pool + take((size_t)3 * P6432);
    float* pW12864 = pool + take((size_t)2 * P12864);
    float* voxs    = pool + take((size_t)N1 * 4);

    auto buf2 = [&](size_t n, float*& b, float*& s) {
        b = pool + take(n); s = pool + take(n);
    };
    float *A, *As, *X1, *X1s, *cat1, *cat1s;
    float *C, *Cs, *Dm, *Dms, *X2, *X2s, *cat2, *cat2s;
    float *Fm, *Fms, *G, *Gs, *X3, *X3s, *cat3, *cat3s;
    float *I, *Is, *J, *Js, *cat4, *cat4s;
    buf2((size_t)N1 * 32, A, As);
    buf2((size_t)N1 * 32, X1, X1s);
    buf2((size_t)N1 * 64, cat1, cat1s);
    buf2((size_t)N2 * 32, C, Cs);
    buf2((size_t)N2 * 32, Dm, Dms);
    buf2((size_t)N2 * 32, X2, X2s);
    buf2((size_t)N2 * 64, cat2, cat2s);
    buf2((size_t)N3 * 64, Fm, Fms);
    buf2((size_t)N3 * 64, G, Gs);
    buf2((size_t)N3 * 64, X3, X3s);
    buf2((size_t)N3 * 128, cat3, cat3s);
    buf2((size_t)N4 * 64, I, Is);
    buf2((size_t)N4 * 64, J, Js);
    buf2((size_t)N4 * 128, cat4, cat4s);

    float* outp = (float*)d_out;

    // ---- prologue: batched weight packing + voxel cvt (7 launches) ----
    pack_launch<4, 32>(Win, pWin, 1);
    pack_launch<32, 32>(W32, pW32, 10);
    pack_launch<64, 64>(W64, pW64, 10);
    pack_launch<32, 64>(Wd3, pWd3, 1);
    pack_launch<64, 32>(W6432, pW6432, 3);
    pack_launch<128, 64>(W12864, pW12864, 2);
    cvt_tf32_kernel<<<(N1 * 4 + 255) / 256, 256>>>(voxel, voxs, N1 * 4);

    // ---- Encoder ----
    conv_launch<4, 32>(voxs, 4, nbr1, pWin, bn32 + 0 * 64, nullptr, 0, nullptr, 0, A, 32, As, N1);
    conv_launch<32, 32>(As, 32, nbr1, pW32 + 0 * (size_t)P32, bn32 + 1 * 64, nullptr, 0, nullptr, 0, X1, 32, X1s, N1);
    conv_launch<32, 32>(X1s, 32, nbrd2, pW32 + 1 * (size_t)P32, bn32 + 2 * 64, nullptr, 0, nullptr, 0, C, 32, Cs, N2);
    conv_launch<32, 32>(Cs, 32, nbr2, pW32 + 2 * (size_t)P32, bn32 + 3 * 64, nullptr, 0, nullptr, 0, Dm, 32, Dms, N2);
    conv_launch<32, 32>(Dms, 32, nbr2, pW32 + 3 * (size_t)P32, bn32 + 4 * 64, nullptr, 0, nullptr, 0, X2, 32, X2s, N2);
    conv_launch<32, 64>(X2s, 32, nbrd3, pWd3, bn64 + 0 * 128, nullptr, 0, nullptr, 0, Fm, 64, Fms, N3);
    conv_launch<64, 64>(Fms, 64, nbr3, pW64 + 0 * (size_t)P64, bn64 + 1 * 128, nullptr, 0, nullptr, 0, G, 64, Gs, N3);
    conv_launch<64, 64>(Gs, 64, nbr3, pW64 + 1 * (size_t)P64, bn64 + 2 * 128, nullptr, 0, nullptr, 0, X3, 64, X3s, N3);
    conv_launch<64, 64>(X3s, 64, nbrd4, pW64 + 2 * (size_t)P64, bn64 + 3 * 128, nullptr, 0, nullptr, 0, I, 64, Is, N4);
    conv_launch<64, 64>(Is, 64, nbr4, pW64 + 3 * (size_t)P64, bn64 + 4 * 128, nullptr, 0, nullptr, 0, J, 64, Js, N4);
    conv_launch<64, 64>(Js, 64, nbr4, pW64 + 4 * (size_t)P64, bn64 + 5 * 128, nullptr, 0, nullptr, 0, cat4, 128, cat4s, N4);

    // ---- Bottleneck ----
    conv_launch<64, 64>(cat4s, 128, nbr4, pW64 + 5 * (size_t)P64, bn64 + 6 * 128, nullptr, 0, nullptr, 0, I, 64, Is, N4);
    conv_launch<64, 64>(Is, 64, nbr4, pW64 + 6 * (size_t)P64, bn64 + 7 * 128, cat4, 128, nullptr, 0, cat4 + 64, 128, cat4s + 64, N4);
    conv_launch<128, 64>(cat4s, 128, nbr4, pW12864 + 0 * (size_t)P12864, bn64 + 11 * 128, nullptr, 0, cat4, 128, J, 64, Js, N4);

    // ---- Decoder level 3 ----
    conv_launch<64, 64>(Js, 64, nbri4, pW64 + 7 * (size_t)P64, bn64 + 8 * 128, nullptr, 0, nullptr, 0, cat3, 128, cat3s, N3);
    conv_launch<64, 64>(X3s, 64, nbr3, pW64 + 8 * (size_t)P64, bn64 + 9 * 128, nullptr, 0, nullptr, 0, Fm, 64, Fms, N3);
    conv_launch<64, 64>(Fms, 64, nbr3, pW64 + 9 * (size_t)P64, bn64 + 10 * 128, X3, 64, nullptr, 0, cat3 + 64, 128, cat3s + 64, N3);
    conv_launch<128, 64>(cat3s, 128, nbr3, pW12864 + 1 * (size_t)P12864, bn64 + 12 * 128, nullptr, 0, cat3, 128, G, 64, Gs, N3);

    // ---- Decoder level 2 ----
    conv_launch<64, 32>(Gs, 64, nbri3, pW6432 + 0 * (size_t)P6432, bn32 + 11 * 64, nullptr, 0, nullptr, 0, cat2, 64, cat2s, N2);
    conv_launch<32, 32>(X2s, 32, nbr2, pW32 + 4 * (size_t)P32, bn32 + 5 * 64, nullptr, 0, nullptr, 0, C, 32, Cs, N2);
    conv_launch<32, 32>(Cs, 32, nbr2, pW32 + 5 * (size_t)P32, bn32 + 6 * 64, X2, 32, nullptr, 0, cat2 + 32, 64, cat2s + 32, N2);
    conv_launch<64, 32>(cat2s, 64, nbr2, pW6432 + 1 * (size_t)P6432, bn32 + 12 * 64, nullptr, 0, cat2, 64, Dm, 32, Dms, N2);

    // ---- Decoder level 1 ----
    conv_launch<32, 32>(Dms, 32, nbri2, pW32 + 6 * (size_t)P32, bn32 + 7 * 64, nullptr, 0, nullptr, 0, cat1, 64, cat1s, N1);
    conv_launch<32, 32>(X1s, 32, nbr1, pW32 + 7 * (size_t)P32, bn32 + 8 * 64, nullptr, 0, nullptr, 0, A, 32, As, N1);
    conv_launch<32, 32>(As, 32, nbr1, pW32 + 8 * (size_t)P32, bn32 + 9 * 64, X1, 32, nullptr, 0, cat1 + 32, 64, cat1s + 32, N1);
    conv_launch<64, 32>(cat1s, 64, nbr1, pW6432 + 2 * (size_t)P6432, bn32 + 13 * 64, nullptr, 0, cat1, 64, A, 32, As, N1);

    // ---- Head ----
    conv_launch<32, 32>(As, 32, nbr1, pW32 + 9 * (size_t)P32, bn32 + 10 * 64, nullptr, 0, nullptr, 0, outp, 32, nullptr, N1);
}

// round 13
// speedup vs baseline: 1.8122x; 1.8122x over previous
#include <cuda_runtime.h>
#include <cuda_fp16.h>
#include <cstddef>
#include <cstdint>

// ---------------------------------------------------------------------------
// Sparse 3D UNet forward.  fp16 mma.sync.m16n8k16 (fp32 accum) sparse-conv
// GEMM on the proven R7 pipeline (BM=128, 2-buffer cp.async, snbr in smem).
// fp16 == tf32 in significand bits (11), so accuracy matches the tf32 path
// while halving MMA count, LDS traffic, gather bytes and smem footprint.
// Features carry an fp16 shadow written by the producing epilogue; weights
// are pre-packed to fp16 transposed [n][k] so B fragments load as LDS32.
// ---------------------------------------------------------------------------

__device__ float g_pool[224u * 1024u * 1024u];   // 896 MB scratch (static: legal)

__device__ __forceinline__ void cp_async16(uint32_t dst, const void* src, int nbytes) {
    asm volatile("cp.async.cg.shared.global [%0], [%1], 16, %2;"
                 :: "r"(dst), "l"(src), "r"(nbytes));
}
__device__ __forceinline__ void cp_commit() {
    asm volatile("cp.async.commit_group;");
}
template <int NG> __device__ __forceinline__ void cp_wait() {
    asm volatile("cp.async.wait_group %0;" :: "n"(NG));
}
__device__ __forceinline__ void mma_fp16(float c[4], uint32_t a0, uint32_t a1,
                                         uint32_t a2, uint32_t a3,
                                         uint32_t b0, uint32_t b1) {
    asm volatile(
        "mma.sync.aligned.m16n8k16.row.col.f32.f16.f16.f32 "
        "{%0,%1,%2,%3},{%4,%5,%6,%7},{%8,%9},{%0,%1,%2,%3};"
        : "+f"(c[0]), "+f"(c[1]), "+f"(c[2]), "+f"(c[3])
        : "r"(a0), "r"(a1), "r"(a2), "r"(a3), "r"(b0), "r"(b1));
}

// voxel fp32 [N][4] -> fp16 [N][16] zero-padded
__global__ void cvt_voxel_kernel(const float* __restrict__ in,
                                 __half* __restrict__ out, int n) {
    for (int i = blockIdx.x * blockDim.x + threadIdx.x; i < n * 16;
         i += gridDim.x * blockDim.x) {
        int r = i >> 4, c = i & 15;
        out[i] = (c < 4) ? __float2half_rn(in[r * 4 + c]) : __half(0.f);
    }
}

template <int CIN, int COUT>
struct SpCfg {
    static constexpr int BM  = 128;
    static constexpr int CK  = (CIN < 32) ? 16 : 32;    // k chunk (padded for CIN=4)
    static constexpr int NCH = (CIN + CK - 1) / CK;
    static constexpr int SPH = CK + 8;                  // feat row stride (halves)
    static constexpr int SKW = CK + 8;                  // W row stride (halves)
    static constexpr int VR  = CK / 8;                  // 16B vecs per feat row
    static constexpr int NT  = COUT / 8;
    static constexpr int KS  = CK / 16;                 // k16 steps per stage
    static constexpr int SMEM_BYTES =
        (2 * BM * SPH + 2 * COUT * SKW) * 2 + 27 * BM * 4 + 64 * 4;
    static constexpr int PACKED_PER_LAYER = 27 * NCH * COUT * CK;   // halves
};

// Pack W fp32 (L,27,CIN,COUT) -> fp16 transposed [l][k][ch][n][kk], zero pad.
template <int CIN, int COUT>
__global__ void pack_w_kernel(const float* __restrict__ W, __half* __restrict__ Wt,
                              int layers) {
    using C = SpCfg<CIN, COUT>;
    const int per = C::PACKED_PER_LAYER;
    const int total = layers * per;
    const size_t src_per = 27u * CIN * COUT;
    for (int o = blockIdx.x * blockDim.x + threadIdx.x; o < total;
         o += gridDim.x * blockDim.x) {
        int l = o / per;
        int q = o - l * per;
        int kk = q % C::CK;
        int rest = q / C::CK;
        int n  = rest % COUT; rest /= COUT;
        int ch = rest % C::NCH;
        int k  = rest / C::NCH;
        int ci = ch * C::CK + kk;
        float v = (ci < CIN)
            ? W[(size_t)l * src_per + ((size_t)k * CIN + ci) * COUT + n] : 0.f;
        Wt[o] = __float2half_rn(v);
    }
}

template <int CIN, int COUT>
__global__ void __launch_bounds__(256)
spconv_mma(const __half* __restrict__ feat, int ldf,  // fp16 shadow input
           const int* __restrict__ nbr,
           const __half* __restrict__ Wt,             // packed fp16 weights
           const float* __restrict__ sb,
           const float* __restrict__ resid, int ldr,  // fp32
           const float* __restrict__ red,   int ldred,
           float* __restrict__ out, int ldo,
           __half* __restrict__ outs,                 // fp16 shadow out (or null)
           int N)
{
    using C = SpCfg<CIN, COUT>;
    constexpr int BM = C::BM, CK = C::CK, NCH = C::NCH;
    constexpr int SPH = C::SPH, SKW = C::SKW, VR = C::VR;
    constexpr int NT = C::NT, KS = C::KS;

    extern __shared__ char smem_raw[];
    __half* sfeat = (__half*)smem_raw;                     // [2][BM*SPH]
    __half* sW    = sfeat + 2 * BM * SPH;                  // [2][COUT*SKW]
    int*    snbr  = (int*)(sW + 2 * COUT * SKW);           // [27*BM]
    int*    kmeta = snbr + 27 * BM;
    int*    khit  = kmeta;
    int*    klist = kmeta + 27;
    int*    knp   = kmeta + 54;

    const uint32_t sfeat_sa = (uint32_t)__cvta_generic_to_shared(sfeat);
    const uint32_t sW_sa    = (uint32_t)__cvta_generic_to_shared(sW);

    const int tid  = threadIdx.x;
    const int lane = tid & 31;
    const int wid  = tid >> 5;
    const int row0 = blockIdx.x * BM;

    // Stage neighbor indices
    for (int e = tid; e < BM * 27; e += 256) {
        int r = e / 27, k = e - r * 27;
        int g = row0 + r;
        snbr[k * BM + r] = (g < N) ? nbr[(size_t)g * 27 + k] : -1;
    }
    __syncthreads();
    if (tid < 27) {
        int h = 0;
        for (int r = 0; r < BM && !h; ++r) h = (snbr[tid * BM + r] >= 0);
        khit[tid] = h;
    }
    __syncthreads();
    if (tid == 0) {
        int n = 0;
        for (int k = 0; k < 27; ++k) if (khit[k]) klist[n++] = k;
        *knp = n;
    }
    __syncthreads();
    const int NS = (*knp) * NCH;

    float acc[NT][4];
#pragma unroll
    for (int t = 0; t < NT; ++t)
#pragma unroll
        for (int j = 0; j < 4; ++j) acc[t][j] = 0.f;

    auto stage = [&](int s) {
        const int k  = klist[s / NCH];
        const int ch = s - (s / NCH) * NCH;
        const int kb = s & 1;
        const uint32_t fb = sfeat_sa + (uint32_t)(kb * BM * SPH) * 2u;
        for (int u = tid; u < BM * VR; u += 256) {
            int r = u / VR, v = u - r * VR;
            int idx = snbr[k * BM + r];
            const __half* g = feat + (size_t)(idx < 0 ? 0 : idx) * ldf
                            + ch * CK + v * 8;
            cp_async16(fb + (uint32_t)(r * SPH + v * 8) * 2u, g, idx < 0 ? 0 : 16);
        }
        const __half* wg = Wt + (size_t)(k * NCH + ch) * COUT * CK;
        const uint32_t wb = sW_sa + (uint32_t)(kb * COUT * SKW) * 2u;
        for (int u = tid; u < COUT * CK / 8; u += 256) {
            int n = u / (CK / 8), c = u - n * (CK / 8);
            cp_async16(wb + (uint32_t)(n * SKW + c * 8) * 2u, wg + n * CK + c * 8, 16);
        }
    };

    const int mrow = wid * 16 + (lane >> 2);
    const int kq   = lane & 3;
    const int nq   = lane >> 2;

    if (NS > 0) {
        stage(0);
        cp_commit();
        for (int s = 0; s < NS; ++s) {
            if (s + 1 < NS) { stage(s + 1); cp_commit(); cp_wait<1>(); }
            else            { cp_wait<0>(); }
            __syncthreads();

            const __half* fb = sfeat + (s & 1) * BM * SPH;
            const __half* wb = sW    + (s & 1) * COUT * SKW;
#pragma unroll
            for (int k16 = 0; k16 < KS; ++k16) {
                const int kc = k16 * 16;
                const __half* fr = fb + mrow * SPH + kc + 2 * kq;
                uint32_t a0 = *(const uint32_t*)(fr);
                uint32_t a1 = *(const uint32_t*)(fr + 8 * SPH);
                uint32_t a2 = *(const uint32_t*)(fr + 8);
                uint32_t a3 = *(const uint32_t*)(fr + 8 * SPH + 8);
#pragma unroll
                for (int t = 0; t < NT; ++t) {
                    const __half* bp = wb + (t * 8 + nq) * SKW + kc + 2 * kq;
                    uint32_t b0 = *(const uint32_t*)(bp);
                    uint32_t b1 = *(const uint32_t*)(bp + 8);
                    mma_fp16(acc[t], a0, a1, a2, a3, b0, b1);
                }
            }
            __syncthreads();
        }
    }

    // -------- epilogue --------
    const int r0 = row0 + mrow;
#pragma unroll
    for (int t = 0; t < NT; ++t) {
        const int col = t * 8 + 2 * kq;
        const float s0 = sb[col],        s1 = sb[col + 1];
        const float b0 = sb[COUT + col], b1 = sb[COUT + col + 1];
#pragma unroll
        for (int h = 0; h < 2; ++h) {
            const int r = r0 + 8 * h;
            if (r >= N) continue;
            float v0 = acc[t][2 * h]     * s0 + b0;
            float v1 = acc[t][2 * h + 1] * s1 + b1;
            if (resid) {
                float2 rr = *(const float2*)(resid + (size_t)r * ldr + col);
                v0 += rr.x; v1 += rr.y;
            }
            v0 = fmaxf(v0, 0.f);
            v1 = fmaxf(v1, 0.f);
            if (red) {
                float4 ra = *(const float4*)(red + (size_t)r * ldred + 2 * col);
                v0 += ra.x + ra.y;
                v1 += ra.z + ra.w;
            }
            *(float2*)(out + (size_t)r * ldo + col) = make_float2(v0, v1);
            if (outs)
                *(__half2*)(outs + (size_t)r * ldo + col) =
                    __floats2half2_rn(v0, v1);
        }
    }
}

template <int CIN, int COUT>
static void conv_launch(const __half* feat, int ldf, const int* nbr,
                        const __half* Wt, const float* sb,
                        const float* resid, int ldr,
                        const float* red, int ldred,
                        float* out, int ldo, __half* outs, int N)
{
    constexpr int SM = SpCfg<CIN, COUT>::SMEM_BYTES;
    cudaFuncSetAttribute(spconv_mma<CIN, COUT>,
                         cudaFuncAttributeMaxDynamicSharedMemorySize, SM);
    const int grid = (N + 127) / 128;
    spconv_mma<CIN, COUT><<<grid, 256, SM>>>(
        feat, ldf, nbr, Wt, sb, resid, ldr, red, ldred, out, ldo, outs, N);
}

template <int CIN, int COUT>
static void pack_launch(const float* W, __half* Wt, int layers)
{
    constexpr int per = SpCfg<CIN, COUT>::PACKED_PER_LAYER;
    const int total = layers * per;
    pack_w_kernel<CIN, COUT><<<(total + 255) / 256, 256>>>(W, Wt, layers);
}

extern "C" void kernel_launch(void* const* d_in, const int* in_sizes, int n_in,
                              void* d_out, int out_size)
{
    const float* voxel  = (const float*)d_in[0];
    const float* Win    = (const float*)d_in[1];
    const float* W32    = (const float*)d_in[2];
    const float* W64    = (const float*)d_in[3];
    const float* Wd3    = (const float*)d_in[4];
    const float* W6432  = (const float*)d_in[5];
    const float* W12864 = (const float*)d_in[6];
    const float* bn32   = (const float*)d_in[7];
    const float* bn64   = (const float*)d_in[8];
    const int* nbr1  = (const int*)d_in[9];
    const int* nbr2  = (const int*)d_in[10];
    const int* nbr3  = (const int*)d_in[11];
    const int* nbr4  = (const int*)d_in[12];
    const int* nbrd2 = (const int*)d_in[13];
    const int* nbrd3 = (const int*)d_in[14];
    const int* nbrd4 = (const int*)d_in[15];
    const int* nbri4 = (const int*)d_in[16];
    const int* nbri3 = (const int*)d_in[17];
    const int* nbri2 = (const int*)d_in[18];

    const int N1 = in_sizes[9]  / 27;
    const int N2 = in_sizes[10] / 27;
    const int N3 = in_sizes[11] / 27;
    const int N4 = in_sizes[12] / 27;

    float* pool = nullptr;
    cudaGetSymbolAddress((void**)&pool, g_pool);

    size_t o = 0;   // float units
    auto takeF = [&](size_t n) { size_t r = o; o += (n + 255) & ~(size_t)255; return pool + r; };
    auto takeH = [&](size_t nh) { return (__half*)takeF((nh + 1) / 2); };

    // ---- packed fp16 weights ----
    constexpr int Pin    = SpCfg<4, 32>::PACKED_PER_LAYER;
    constexpr int P32    = SpCfg<32, 32>::PACKED_PER_LAYER;
    constexpr int P64    = SpCfg<64, 64>::PACKED_PER_LAYER;
    constexpr int Pd3    = SpCfg<32, 64>::PACKED_PER_LAYER;
    constexpr int P6432  = SpCfg<64, 32>::PACKED_PER_LAYER;
    constexpr int P12864 = SpCfg<128, 64>::PACKED_PER_LAYER;
    __half* pWin    = takeH(Pin);
    __half* pW32    = takeH((size_t)10 * P32);
    __half* pW64    = takeH((size_t)10 * P64);
    __half* pWd3    = takeH(Pd3);
    __half* pW6432  = takeH((size_t)3 * P6432);
    __half* pW12864 = takeH((size_t)2 * P12864);
    __half* voxs    = takeH((size_t)N1 * 16);     // zero-padded to 16 channels

    // ---- feature buffers: fp32 + fp16 shadow ----
    float *A, *X1, *cat1, *C, *Dm, *X2, *cat2, *Fm, *G, *X3, *cat3, *I, *J, *cat4;
    __half *As, *X1s, *cat1s, *Cs, *Dms, *X2s, *cat2s, *Fms, *Gs, *X3s, *cat3s,
           *Is, *Js, *cat4s;
    auto buf2 = [&](size_t n, float*& b, __half*& s) {
        b = takeF(n); s = takeH(n);
    };
    buf2((size_t)N1 * 32, A, As);
    buf2((size_t)N1 * 32, X1, X1s);
    buf2((size_t)N1 * 64, cat1, cat1s);
    buf2((size_t)N2 * 32, C, Cs);
    buf2((size_t)N2 * 32, Dm, Dms);
    buf2((size_t)N2 * 32, X2, X2s);
    buf2((size_t)N2 * 64, cat2, cat2s);
    buf2((size_t)N3 * 64, Fm, Fms);
    buf2((size_t)N3 * 64, G, Gs);
    buf2((size_t)N3 * 64, X3, X3s);
    buf2((size_t)N3 * 128, cat3, cat3s);
    buf2((size_t)N4 * 64, I, Is);
    buf2((size_t)N4 * 64, J, Js);
    buf2((size_t)N4 * 128, cat4, cat4s);

    float* outp = (float*)d_out;

    // ---- prologue: batched fp16 weight packing + padded voxel cvt ----
    pack_launch<4, 32>(Win, pWin, 1);
    pack_launch<32, 32>(W32, pW32, 10);
    pack_launch<64, 64>(W64, pW64, 10);
    pack_launch<32, 64>(Wd3, pWd3, 1);
    pack_launch<64, 32>(W6432, pW6432, 3);
    pack_launch<128, 64>(W12864, pW12864, 2);
    cvt_voxel_kernel<<<(N1 * 16 + 255) / 256, 256>>>(voxel, voxs, N1);

    // ---- Encoder ----
    conv_launch<4, 32>(voxs, 16, nbr1, pWin, bn32 + 0 * 64, nullptr, 0, nullptr, 0, A, 32, As, N1);
    conv_launch<32, 32>(As, 32, nbr1, pW32 + 0 * (size_t)P32, bn32 + 1 * 64, nullptr, 0, nullptr, 0, X1, 32, X1s, N1);
    conv_launch<32, 32>(X1s, 32, nbrd2, pW32 + 1 * (size_t)P32, bn32 + 2 * 64, nullptr, 0, nullptr, 0, C, 32, Cs, N2);
    conv_launch<32, 32>(Cs, 32, nbr2, pW32 + 2 * (size_t)P32, bn32 + 3 * 64, nullptr, 0, nullptr, 0, Dm, 32, Dms, N2);
    conv_launch<32, 32>(Dms, 32, nbr2, pW32 + 3 * (size_t)P32, bn32 + 4 * 64, nullptr, 0, nullptr, 0, X2, 32, X2s, N2);
    conv_launch<32, 64>(X2s, 32, nbrd3, pWd3, bn64 + 0 * 128, nullptr, 0, nullptr, 0, Fm, 64, Fms, N3);
    conv_launch<64, 64>(Fms, 64, nbr3, pW64 + 0 * (size_t)P64, bn64 + 1 * 128, nullptr, 0, nullptr, 0, G, 64, Gs, N3);
    conv_launch<64, 64>(Gs, 64, nbr3, pW64 + 1 * (size_t)P64, bn64 + 2 * 128, nullptr, 0, nullptr, 0, X3, 64, X3s, N3);
    conv_launch<64, 64>(X3s, 64, nbrd4, pW64 + 2 * (size_t)P64, bn64 + 3 * 128, nullptr, 0, nullptr, 0, I, 64, Is, N4);
    conv_launch<64, 64>(Is, 64, nbr4, pW64 + 3 * (size_t)P64, bn64 + 4 * 128, nullptr, 0, nullptr, 0, J, 64, Js, N4);
    conv_launch<64, 64>(Js, 64, nbr4, pW64 + 4 * (size_t)P64, bn64 + 5 * 128, nullptr, 0, nullptr, 0, cat4, 128, cat4s, N4);

    // ---- Bottleneck ----
    conv_launch<64, 64>(cat4s, 128, nbr4, pW64 + 5 * (size_t)P64, bn64 + 6 * 128, nullptr, 0, nullptr, 0, I, 64, Is, N4);
    conv_launch<64, 64>(Is, 64, nbr4, pW64 + 6 * (size_t)P64, bn64 + 7 * 128, cat4, 128, nullptr, 0, cat4 + 64, 128, cat4s + 64, N4);
    conv_launch<128, 64>(cat4s, 128, nbr4, pW12864 + 0 * (size_t)P12864, bn64 + 11 * 128, nullptr, 0, cat4, 128, J, 64, Js, N4);

    // ---- Decoder level 3 ----
    conv_launch<64, 64>(Js, 64, nbri4, pW64 + 7 * (size_t)P64, bn64 + 8 * 128, nullptr, 0, nullptr, 0, cat3, 128, cat3s, N3);
    conv_launch<64, 64>(X3s, 64, nbr3, pW64 + 8 * (size_t)P64, bn64 + 9 * 128, nullptr, 0, nullptr, 0, Fm, 64, Fms, N3);
    conv_launch<64, 64>(Fms, 64, nbr3, pW64 + 9 * (size_t)P64, bn64 + 10 * 128, X3, 64, nullptr, 0, cat3 + 64, 128, cat3s + 64, N3);
    conv_launch<128, 64>(cat3s, 128, nbr3, pW12864 + 1 * (size_t)P12864, bn64 + 12 * 128, nullptr, 0, cat3, 128, G, 64, Gs, N3);

    // ---- Decoder level 2 ----
    conv_launch<64, 32>(Gs, 64, nbri3, pW6432 + 0 * (size_t)P6432, bn32 + 11 * 64, nullptr, 0, nullptr, 0, cat2, 64, cat2s, N2);
    conv_launch<32, 32>(X2s, 32, nbr2, pW32 + 4 * (size_t)P32, bn32 + 5 * 64, nullptr, 0, nullptr, 0, C, 32, Cs, N2);
    conv_launch<32, 32>(Cs, 32, nbr2, pW32 + 5 * (size_t)P32, bn32 + 6 * 64, X2, 32, nullptr, 0, cat2 + 32, 64, cat2s + 32, N2);
    conv_launch<64, 32>(cat2s, 64, nbr2, pW6432 + 1 * (size_t)P6432, bn32 + 12 * 64, nullptr, 0, cat2, 64, Dm, 32, Dms, N2);

    // ---- Decoder level 1 ----
    conv_launch<32, 32>(Dms, 32, nbri2, pW32 + 6 * (size_t)P32, bn32 + 7 * 64, nullptr, 0, nullptr, 0, cat1, 64, cat1s, N1);
    conv_launch<32, 32>(X1s, 32, nbr1, pW32 + 7 * (size_t)P32, bn32 + 8 * 64, nullptr, 0, nullptr, 0, A, 32, As, N1);
    conv_launch<32, 32>(As, 32, nbr1, pW32 + 8 * (size_t)P32, bn32 + 9 * 64, X1, 32, nullptr, 0, cat1 + 32, 64, cat1s + 32, N1);
    conv_launch<64, 32>(cat1s, 64, nbr1, pW6432 + 2 * (size_t)P6432, bn32 + 13 * 64, nullptr, 0, cat1, 64, A, 32, As, N1);

    // ---- Head ----
    conv_launch<32, 32>(As, 32, nbr1, pW32 + 9 * (size_t)P32, bn32 + 10 * 64, nullptr, 0, nullptr, 0, outp, 32, nullptr, N1);
}

// round 14
// speedup vs baseline: 1.8928x; 1.0445x over previous
#include <cuda_runtime.h>
#include <cuda_fp16.h>
#include <cstddef>
#include <cstdint>

// ---------------------------------------------------------------------------
// Sparse 3D UNet forward.  fp16 mma.sync.m16n8k16 (fp32 accum) sparse conv.
// R14 = R13 + ldmatrix fragment loads: A via one LDSM.x4, B via one LDSM.x4
// per PAIR of n-tiles (weights stored [n][k] so non-trans ldmatrix yields the
// exact mma B register layout).  Mainloop LDS issue count cut ~2.2x.
// ---------------------------------------------------------------------------

__device__ float g_pool[224u * 1024u * 1024u];   // 896 MB scratch (static: legal)

__device__ __forceinline__ void cp_async16(uint32_t dst, const void* src, int nbytes) {
    asm volatile("cp.async.cg.shared.global [%0], [%1], 16, %2;"
                 :: "r"(dst), "l"(src), "r"(nbytes));
}
__device__ __forceinline__ void cp_commit() {
    asm volatile("cp.async.commit_group;");
}
template <int NG> __device__ __forceinline__ void cp_wait() {
    asm volatile("cp.async.wait_group %0;" :: "n"(NG));
}
__device__ __forceinline__ void ldsm_x4(uint32_t& r0, uint32_t& r1,
                                        uint32_t& r2, uint32_t& r3, uint32_t addr) {
    asm volatile("ldmatrix.sync.aligned.m8n8.x4.shared.b16 {%0,%1,%2,%3}, [%4];"
                 : "=r"(r0), "=r"(r1), "=r"(r2), "=r"(r3) : "r"(addr));
}
__device__ __forceinline__ void mma_fp16(float c[4], uint32_t a0, uint32_t a1,
                                         uint32_t a2, uint32_t a3,
                                         uint32_t b0, uint32_t b1) {
    asm volatile(
        "mma.sync.aligned.m16n8k16.row.col.f32.f16.f16.f32 "
        "{%0,%1,%2,%3},{%4,%5,%6,%7},{%8,%9},{%0,%1,%2,%3};"
        : "+f"(c[0]), "+f"(c[1]), "+f"(c[2]), "+f"(c[3])
        : "r"(a0), "r"(a1), "r"(a2), "r"(a3), "r"(b0), "r"(b1));
}

// voxel fp32 [N][4] -> fp16 [N][16] zero-padded
__global__ void cvt_voxel_kernel(const float* __restrict__ in,
                                 __half* __restrict__ out, int n) {
    for (int i = blockIdx.x * blockDim.x + threadIdx.x; i < n * 16;
         i += gridDim.x * blockDim.x) {
        int r = i >> 4, c = i & 15;
        out[i] = (c < 4) ? __float2half_rn(in[r * 4 + c]) : __half(0.f);
    }
}

template <int CIN, int COUT>
struct SpCfg {
    static constexpr int BM  = 128;
    static constexpr int CK  = (CIN < 32) ? 16 : 32;    // k chunk (padded for CIN=4)
    static constexpr int NCH = (CIN + CK - 1) / CK;
    static constexpr int SPH = CK + 8;                  // feat row stride (halves)
    static constexpr int SKW = CK + 8;                  // W row stride (halves)
    static constexpr int VR  = CK / 8;                  // 16B vecs per feat row
    static constexpr int NT  = COUT / 8;                // n-tiles (4 or 8)
    static constexpr int NP2 = NT / 2;                  // n-tile pairs
    static constexpr int KS  = CK / 16;                 // k16 steps per stage
    static constexpr int SMEM_BYTES =
        (2 * BM * SPH + 2 * COUT * SKW) * 2 + 27 * BM * 4 + 64 * 4;
    static constexpr int PACKED_PER_LAYER = 27 * NCH * COUT * CK;   // halves
};

// Pack W fp32 (L,27,CIN,COUT) -> fp16 transposed [l][k][ch][n][kk], zero pad.
template <int CIN, int COUT>
__global__ void pack_w_kernel(const float* __restrict__ W, __half* __restrict__ Wt,
                              int layers) {
    using C = SpCfg<CIN, COUT>;
    const int per = C::PACKED_PER_LAYER;
    const int total = layers * per;
    const size_t src_per = 27u * CIN * COUT;
    for (int o = blockIdx.x * blockDim.x + threadIdx.x; o < total;
         o += gridDim.x * blockDim.x) {
        int l = o / per;
        int q = o - l * per;
        int kk = q % C::CK;
        int rest = q / C::CK;
        int n  = rest % COUT; rest /= COUT;
        int ch = rest % C::NCH;
        int k  = rest / C::NCH;
        int ci = ch * C::CK + kk;
        float v = (ci < CIN)
            ? W[(size_t)l * src_per + ((size_t)k * CIN + ci) * COUT + n] : 0.f;
        Wt[o] = __float2half_rn(v);
    }
}

template <int CIN, int COUT>
__global__ void __launch_bounds__(256)
spconv_mma(const __half* __restrict__ feat, int ldf,  // fp16 shadow input
           const int* __restrict__ nbr,
           const __half* __restrict__ Wt,             // packed fp16 weights
           const float* __restrict__ sb,
           const float* __restrict__ resid, int ldr,  // fp32
           const float* __restrict__ red,   int ldred,
           float* __restrict__ out, int ldo,
           __half* __restrict__ outs,                 // fp16 shadow out (or null)
           int N)
{
    using C = SpCfg<CIN, COUT>;
    constexpr int BM = C::BM, CK = C::CK, NCH = C::NCH;
    constexpr int SPH = C::SPH, SKW = C::SKW, VR = C::VR;
    constexpr int NT = C::NT, NP2 = C::NP2, KS = C::KS;

    extern __shared__ char smem_raw[];
    __half* sfeat = (__half*)smem_raw;                     // [2][BM*SPH]
    __half* sW    = sfeat + 2 * BM * SPH;                  // [2][COUT*SKW]
    int*    snbr  = (int*)(sW + 2 * COUT * SKW);           // [27*BM]
    int*    kmeta = snbr + 27 * BM;
    int*    khit  = kmeta;
    int*    klist = kmeta + 27;
    int*    knp   = kmeta + 54;

    const uint32_t sfeat_sa = (uint32_t)__cvta_generic_to_shared(sfeat);
    const uint32_t sW_sa    = (uint32_t)__cvta_generic_to_shared(sW);

    const int tid  = threadIdx.x;
    const int lane = tid & 31;
    const int wid  = tid >> 5;
    const int row0 = blockIdx.x * BM;

    // Stage neighbor indices
    for (int e = tid; e < BM * 27; e += 256) {
        int r = e / 27, k = e - r * 27;
        int g = row0 + r;
        snbr[k * BM + r] = (g < N) ? nbr[(size_t)g * 27 + k] : -1;
    }
    __syncthreads();
    if (tid < 27) {
        int h = 0;
        for (int r = 0; r < BM && !h; ++r) h = (snbr[tid * BM + r] >= 0);
        khit[tid] = h;
    }
    __syncthreads();
    if (tid == 0) {
        int n = 0;
        for (int k = 0; k < 27; ++k) if (khit[k]) klist[n++] = k;
        *knp = n;
    }
    __syncthreads();
    const int NS = (*knp) * NCH;

    float acc[NT][4];
#pragma unroll
    for (int t = 0; t < NT; ++t)
#pragma unroll
        for (int j = 0; j < 4; ++j) acc[t][j] = 0.f;

    auto stage = [&](int s) {
        const int k  = klist[s / NCH];
        const int ch = s - (s / NCH) * NCH;
        const int kb = s & 1;
        const uint32_t fb = sfeat_sa + (uint32_t)(kb * BM * SPH) * 2u;
        for (int u = tid; u < BM * VR; u += 256) {
            int r = u / VR, v = u - r * VR;
            int idx = snbr[k * BM + r];
            const __half* g = feat + (size_t)(idx < 0 ? 0 : idx) * ldf
                            + ch * CK + v * 8;
            cp_async16(fb + (uint32_t)(r * SPH + v * 8) * 2u, g, idx < 0 ? 0 : 16);
        }
        const __half* wg = Wt + (size_t)(k * NCH + ch) * COUT * CK;
        const uint32_t wb = sW_sa + (uint32_t)(kb * COUT * SKW) * 2u;
        for (int u = tid; u < COUT * CK / 8; u += 256) {
            int n = u / (CK / 8), c = u - n * (CK / 8);
            cp_async16(wb + (uint32_t)(n * SKW + c * 8) * 2u, wg + n * CK + c * 8, 16);
        }
    };

    const int mrow = wid * 16 + (lane >> 2);
    const int kq   = lane & 3;

    // ldmatrix per-thread address offsets (halves), hoisted out of the loop.
    // A x4 tiles: (r0-7,k0-7),(r8-15,k0-7),(r0-7,k8-15),(r8-15,k8-15)
    const uint32_t a_off =
        (uint32_t)((wid * 16 + (lane & 7) + ((lane >> 3) & 1) * 8) * SPH
                   + (lane >> 4) * 8) * 2u;
    // B x4 tiles for pair p: (n 8t..,k0-7),(n 8t..,k8-15),(n 8t+8..,k0-7),(n 8t+8..,k8-15)
    uint32_t b_off[NP2];
#pragma unroll
    for (int p = 0; p < NP2; ++p)
        b_off[p] = (uint32_t)(((p * 16 + ((lane >> 4) & 1) * 8 + (lane & 7)) * SKW)
                              + ((lane >> 3) & 1) * 8) * 2u;

    if (NS > 0) {
        stage(0);
        cp_commit();
        for (int s = 0; s < NS; ++s) {
            if (s + 1 < NS) { stage(s + 1); cp_commit(); cp_wait<1>(); }
            else            { cp_wait<0>(); }
            __syncthreads();

            const uint32_t fb = sfeat_sa + (uint32_t)((s & 1) * BM * SPH) * 2u;
            const uint32_t wb = sW_sa    + (uint32_t)((s & 1) * COUT * SKW) * 2u;
#pragma unroll
            for (int k16 = 0; k16 < KS; ++k16) {
                const uint32_t kco = (uint32_t)(k16 * 16) * 2u;
                uint32_t a0, a1, a2, a3;
                ldsm_x4(a0, a1, a2, a3, fb + a_off + kco);
#pragma unroll
                for (int p = 0; p < NP2; ++p) {
                    uint32_t b00, b01, b10, b11;
                    ldsm_x4(b00, b01, b10, b11, wb + b_off[p] + kco);
                    mma_fp16(acc[2 * p],     a0, a1, a2, a3, b00, b01);
                    mma_fp16(acc[2 * p + 1], a0, a1, a2, a3, b10, b11);
                }
            }
            __syncthreads();
        }
    }

    // -------- epilogue --------
    const int r0 = row0 + mrow;
#pragma unroll
    for (int t = 0; t < NT; ++t) {
        const int col = t * 8 + 2 * kq;
        const float s0 = sb[col],        s1 = sb[col + 1];
        const float b0 = sb[COUT + col], b1 = sb[COUT + col + 1];
#pragma unroll
        for (int h = 0; h < 2; ++h) {
            const int r = r0 + 8 * h;
            if (r >= N) continue;
            float v0 = acc[t][2 * h]     * s0 + b0;
            float v1 = acc[t][2 * h + 1] * s1 + b1;
            if (resid) {
                float2 rr = *(const float2*)(resid + (size_t)r * ldr + col);
                v0 += rr.x; v1 += rr.y;
            }
            v0 = fmaxf(v0, 0.f);
            v1 = fmaxf(v1, 0.f);
            if (red) {
                float4 ra = *(const float4*)(red + (size_t)r * ldred + 2 * col);
                v0 += ra.x + ra.y;
                v1 += ra.z + ra.w;
            }
            *(float2*)(out + (size_t)r * ldo + col) = make_float2(v0, v1);
            if (outs)
                *(__half2*)(outs + (size_t)r * ldo + col) =
                    __floats2half2_rn(v0, v1);
        }
    }
}

template <int CIN, int COUT>
static void conv_launch(const __half* feat, int ldf, const int* nbr,
                        const __half* Wt, const float* sb,
                        const float* resid, int ldr,
                        const float* red, int ldred,
                        float* out, int ldo, __half* outs, int N)
{
    constexpr int SM = SpCfg<CIN, COUT>::SMEM_BYTES;
    cudaFuncSetAttribute(spconv_mma<CIN, COUT>,
                         cudaFuncAttributeMaxDynamicSharedMemorySize, SM);
    const int grid = (N + 127) / 128;
    spconv_mma<CIN, COUT><<<grid, 256, SM>>>(
        feat, ldf, nbr, Wt, sb, resid, ldr, red, ldred, out, ldo, outs, N);
}

template <int CIN, int COUT>
static void pack_launch(const float* W, __half* Wt, int layers)
{
    constexpr int per = SpCfg<CIN, COUT>::PACKED_PER_LAYER;
    const int total = layers * per;
    pack_w_kernel<CIN, COUT><<<(total + 255) / 256, 256>>>(W, Wt, layers);
}

extern "C" void kernel_launch(void* const* d_in, const int* in_sizes, int n_in,
                              void* d_out, int out_size)
{
    const float* voxel  = (const float*)d_in[0];
    const float* Win    = (const float*)d_in[1];
    const float* W32    = (const float*)d_in[2];
    const float* W64    = (const float*)d_in[3];
    const float* Wd3    = (const float*)d_in[4];
    const float* W6432  = (const float*)d_in[5];
    const float* W12864 = (const float*)d_in[6];
    const float* bn32   = (const float*)d_in[7];
    const float* bn64   = (const float*)d_in[8];
    const int* nbr1  = (const int*)d_in[9];
    const int* nbr2  = (const int*)d_in[10];
    const int* nbr3  = (const int*)d_in[11];
    const int* nbr4  = (const int*)d_in[12];
    const int* nbrd2 = (const int*)d_in[13];
    const int* nbrd3 = (const int*)d_in[14];
    const int* nbrd4 = (const int*)d_in[15];
    const int* nbri4 = (const int*)d_in[16];
    const int* nbri3 = (const int*)d_in[17];
    const int* nbri2 = (const int*)d_in[18];

    const int N1 = in_sizes[9]  / 27;
    const int N2 = in_sizes[10] / 27;
    const int N3 = in_sizes[11] / 27;
    const int N4 = in_sizes[12] / 27;

    float* pool = nullptr;
    cudaGetSymbolAddress((void**)&pool, g_pool);

    size_t o = 0;   // float units
    auto takeF = [&](size_t n) { size_t r = o; o += (n + 255) & ~(size_t)255; return pool + r; };
    auto takeH = [&](size_t nh) { return (__half*)takeF((nh + 1) / 2); };

    // ---- packed fp16 weights ----
    constexpr int Pin    = SpCfg<4, 32>::PACKED_PER_LAYER;
    constexpr int P32    = SpCfg<32, 32>::PACKED_PER_LAYER;
    constexpr int P64    = SpCfg<64, 64>::PACKED_PER_LAYER;
    constexpr int Pd3    = SpCfg<32, 64>::PACKED_PER_LAYER;
    constexpr int P6432  = SpCfg<64, 32>::PACKED_PER_LAYER;
    constexpr int P12864 = SpCfg<128, 64>::PACKED_PER_LAYER;
    __half* pWin    = takeH(Pin);
    __half* pW32    = takeH((size_t)10 * P32);
    __half* pW64    = takeH((size_t)10 * P64);
    __half* pWd3    = takeH(Pd3);
    __half* pW6432  = takeH((size_t)3 * P6432);
    __half* pW12864 = takeH((size_t)2 * P12864);
    __half* voxs    = takeH((size_t)N1 * 16);     // zero-padded to 16 channels

    // ---- feature buffers: fp32 + fp16 shadow ----
    float *A, *X1, *cat1, *C, *Dm, *X2, *cat2, *Fm, *G, *X3, *cat3, *I, *J, *cat4;
    __half *As, *X1s, *cat1s, *Cs, *Dms, *X2s, *cat2s, *Fms, *Gs, *X3s, *cat3s,
           *Is, *Js, *cat4s;
    auto buf2 = [&](size_t n, float*& b, __half*& s) {
        b = takeF(n); s = takeH(n);
    };
    buf2((size_t)N1 * 32, A, As);
    buf2((size_t)N1 * 32, X1, X1s);
    buf2((size_t)N1 * 64, cat1, cat1s);
    buf2((size_t)N2 * 32, C, Cs);
    buf2((size_t)N2 * 32, Dm, Dms);
    buf2((size_t)N2 * 32, X2, X2s);
    buf2((size_t)N2 * 64, cat2, cat2s);
    buf2((size_t)N3 * 64, Fm, Fms);
    buf2((size_t)N3 * 64, G, Gs);
    buf2((size_t)N3 * 64, X3, X3s);
    buf2((size_t)N3 * 128, cat3, cat3s);
    buf2((size_t)N4 * 64, I, Is);
    buf2((size_t)N4 * 64, J, Js);
    buf2((size_t)N4 * 128, cat4, cat4s);

    float* outp = (float*)d_out;

    // ---- prologue: batched fp16 weight packing + padded voxel cvt ----
    pack_launch<4, 32>(Win, pWin, 1);
    pack_launch<32, 32>(W32, pW32, 10);
    pack_launch<64, 64>(W64, pW64, 10);
    pack_launch<32, 64>(Wd3, pWd3, 1);
    pack_launch<64, 32>(W6432, pW6432, 3);
    pack_launch<128, 64>(W12864, pW12864, 2);
    cvt_voxel_kernel<<<(N1 * 16 + 255) / 256, 256>>>(voxel, voxs, N1);

    // ---- Encoder ----
    conv_launch<4, 32>(voxs, 16, nbr1, pWin, bn32 + 0 * 64, nullptr, 0, nullptr, 0, A, 32, As, N1);
    conv_launch<32, 32>(As, 32, nbr1, pW32 + 0 * (size_t)P32, bn32 + 1 * 64, nullptr, 0, nullptr, 0, X1, 32, X1s, N1);
    conv_launch<32, 32>(X1s, 32, nbrd2, pW32 + 1 * (size_t)P32, bn32 + 2 * 64, nullptr, 0, nullptr, 0, C, 32, Cs, N2);
    conv_launch<32, 32>(Cs, 32, nbr2, pW32 + 2 * (size_t)P32, bn32 + 3 * 64, nullptr, 0, nullptr, 0, Dm, 32, Dms, N2);
    conv_launch<32, 32>(Dms, 32, nbr2, pW32 + 3 * (size_t)P32, bn32 + 4 * 64, nullptr, 0, nullptr, 0, X2, 32, X2s, N2);
    conv_launch<32, 64>(X2s, 32, nbrd3, pWd3, bn64 + 0 * 128, nullptr, 0, nullptr, 0, Fm, 64, Fms, N3);
    conv_launch<64, 64>(Fms, 64, nbr3, pW64 + 0 * (size_t)P64, bn64 + 1 * 128, nullptr, 0, nullptr, 0, G, 64, Gs, N3);
    conv_launch<64, 64>(Gs, 64, nbr3, pW64 + 1 * (size_t)P64, bn64 + 2 * 128, nullptr, 0, nullptr, 0, X3, 64, X3s, N3);
    conv_launch<64, 64>(X3s, 64, nbrd4, pW64 + 2 * (size_t)P64, bn64 + 3 * 128, nullptr, 0, nullptr, 0, I, 64, Is, N4);
    conv_launch<64, 64>(Is, 64, nbr4, pW64 + 3 * (size_t)P64, bn64 + 4 * 128, nullptr, 0, nullptr, 0, J, 64, Js, N4);
    conv_launch<64, 64>(Js, 64, nbr4, pW64 + 4 * (size_t)P64, bn64 + 5 * 128, nullptr, 0, nullptr, 0, cat4, 128, cat4s, N4);

    // ---- Bottleneck ----
    conv_launch<64, 64>(cat4s, 128, nbr4, pW64 + 5 * (size_t)P64, bn64 + 6 * 128, nullptr, 0, nullptr, 0, I, 64, Is, N4);
    conv_launch<64, 64>(Is, 64, nbr4, pW64 + 6 * (size_t)P64, bn64 + 7 * 128, cat4, 128, nullptr, 0, cat4 + 64, 128, cat4s + 64, N4);
    conv_launch<128, 64>(cat4s, 128, nbr4, pW12864 + 0 * (size_t)P12864, bn64 + 11 * 128, nullptr, 0, cat4, 128, J, 64, Js, N4);

    // ---- Decoder level 3 ----
    conv_launch<64, 64>(Js, 64, nbri4, pW64 + 7 * (size_t)P64, bn64 + 8 * 128, nullptr, 0, nullptr, 0, cat3, 128, cat3s, N3);
    conv_launch<64, 64>(X3s, 64, nbr3, pW64 + 8 * (size_t)P64, bn64 + 9 * 128, nullptr, 0, nullptr, 0, Fm, 64, Fms, N3);
    conv_launch<64, 64>(Fms, 64, nbr3, pW64 + 9 * (size_t)P64, bn64 + 10 * 128, X3, 64, nullptr, 0, cat3 + 64, 128, cat3s + 64, N3);
    conv_launch<128, 64>(cat3s, 128, nbr3, pW12864 + 1 * (size_t)P12864, bn64 + 12 * 128, nullptr, 0, cat3, 128, G, 64, Gs, N3);

    // ---- Decoder level 2 ----
    conv_launch<64, 32>(Gs, 64, nbri3, pW6432 + 0 * (size_t)P6432, bn32 + 11 * 64, nullptr, 0, nullptr, 0, cat2, 64, cat2s, N2);
    conv_launch<32, 32>(X2s, 32, nbr2, pW32 + 4 * (size_t)P32, bn32 + 5 * 64, nullptr, 0, nullptr, 0, C, 32, Cs, N2);
    conv_launch<32, 32>(Cs, 32, nbr2, pW32 + 5 * (size_t)P32, bn32 + 6 * 64, X2, 32, nullptr, 0, cat2 + 32, 64, cat2s + 32, N2);
    conv_launch<64, 32>(cat2s, 64, nbr2, pW6432 + 1 * (size_t)P6432, bn32 + 12 * 64, nullptr, 0, cat2, 64, Dm, 32, Dms, N2);

    // ---- Decoder level 1 ----
    conv_launch<32, 32>(Dms, 32, nbri2, pW32 + 6 * (size_t)P32, bn32 + 7 * 64, nullptr, 0, nullptr, 0, cat1, 64, cat1s, N1);
    conv_launch<32, 32>(X1s, 32, nbr1, pW32 + 7 * (size_t)P32, bn32 + 8 * 64, nullptr, 0, nullptr, 0, A, 32, As, N1);
    conv_launch<32, 32>(As, 32, nbr1, pW32 + 8 * (size_t)P32, bn32 + 9 * 64, X1, 32, nullptr, 0, cat1 + 32, 64, cat1s + 32, N1);
    conv_launch<64, 32>(cat1s, 64, nbr1, pW6432 + 2 * (size_t)P6432, bn32 + 13 * 64, nullptr, 0, cat1, 64, A, 32, As, N1);

    // ---- Head ----
    conv_launch<32, 32>(As, 32, nbr1, pW32 + 9 * (size_t)P32, bn32 + 10 * 64, nullptr, 0, nullptr, 0, outp, 32, nullptr, N1);
}

// round 15
// speedup vs baseline: 1.9596x; 1.0353x over previous
#include <cuda_runtime.h>
#include <cuda_fp16.h>
#include <cstddef>
#include <cstdint>

// ---------------------------------------------------------------------------
// Sparse 3D UNet forward.  fp16 mma.sync.m16n8k16 (fp32 accum) sparse conv.
// R15 = R14 + CK=64 for CIN>=64: one pipeline stage per kernel offset k for
// the heavy layers (halves barriers / stage overhead; same bytes and MMAs).
// ---------------------------------------------------------------------------

__device__ float g_pool[224u * 1024u * 1024u];   // 896 MB scratch (static: legal)

__device__ __forceinline__ void cp_async16(uint32_t dst, const void* src, int nbytes) {
    asm volatile("cp.async.cg.shared.global [%0], [%1], 16, %2;"
                 :: "r"(dst), "l"(src), "r"(nbytes));
}
__device__ __forceinline__ void cp_commit() {
    asm volatile("cp.async.commit_group;");
}
template <int NG> __device__ __forceinline__ void cp_wait() {
    asm volatile("cp.async.wait_group %0;" :: "n"(NG));
}
__device__ __forceinline__ void ldsm_x4(uint32_t& r0, uint32_t& r1,
                                        uint32_t& r2, uint32_t& r3, uint32_t addr) {
    asm volatile("ldmatrix.sync.aligned.m8n8.x4.shared.b16 {%0,%1,%2,%3}, [%4];"
                 : "=r"(r0), "=r"(r1), "=r"(r2), "=r"(r3) : "r"(addr));
}
__device__ __forceinline__ void mma_fp16(float c[4], uint32_t a0, uint32_t a1,
                                         uint32_t a2, uint32_t a3,
                                         uint32_t b0, uint32_t b1) {
    asm volatile(
        "mma.sync.aligned.m16n8k16.row.col.f32.f16.f16.f32 "
        "{%0,%1,%2,%3},{%4,%5,%6,%7},{%8,%9},{%0,%1,%2,%3};"
        : "+f"(c[0]), "+f"(c[1]), "+f"(c[2]), "+f"(c[3])
        : "r"(a0), "r"(a1), "r"(a2), "r"(a3), "r"(b0), "r"(b1));
}

// voxel fp32 [N][4] -> fp16 [N][16] zero-padded
__global__ void cvt_voxel_kernel(const float* __restrict__ in,
                                 __half* __restrict__ out, int n) {
    for (int i = blockIdx.x * blockDim.x + threadIdx.x; i < n * 16;
         i += gridDim.x * blockDim.x) {
        int r = i >> 4, c = i & 15;
        out[i] = (c < 4) ? __float2half_rn(in[r * 4 + c]) : __half(0.f);
    }
}

template <int CIN, int COUT>
struct SpCfg {
    static constexpr int BM  = 128;
    static constexpr int CK  = (CIN < 32) ? 16 : ((CIN >= 64) ? 64 : 32);
    static constexpr int NCH = (CIN + CK - 1) / CK;
    static constexpr int SPH = CK + 8;                  // feat row stride (halves)
    static constexpr int SKW = CK + 8;                  // W row stride (halves)
    static constexpr int VR  = CK / 8;                  // 16B vecs per feat row
    static constexpr int NT  = COUT / 8;                // n-tiles (4 or 8)
    static constexpr int NP2 = NT / 2;                  // n-tile pairs
    static constexpr int KS  = CK / 16;                 // k16 steps per stage
    static constexpr int SMEM_BYTES =
        (2 * BM * SPH + 2 * COUT * SKW) * 2 + 27 * BM * 4 + 64 * 4;
    static constexpr int PACKED_PER_LAYER = 27 * NCH * COUT * CK;   // halves
};

// Pack W fp32 (L,27,CIN,COUT) -> fp16 transposed [l][k][ch][n][kk], zero pad.
template <int CIN, int COUT>
__global__ void pack_w_kernel(const float* __restrict__ W, __half* __restrict__ Wt,
                              int layers) {
    using C = SpCfg<CIN, COUT>;
    const int per = C::PACKED_PER_LAYER;
    const int total = layers * per;
    const size_t src_per = 27u * CIN * COUT;
    for (int o = blockIdx.x * blockDim.x + threadIdx.x; o < total;
         o += gridDim.x * blockDim.x) {
        int l = o / per;
        int q = o - l * per;
        int kk = q % C::CK;
        int rest = q / C::CK;
        int n  = rest % COUT; rest /= COUT;
        int ch = rest % C::NCH;
        int k  = rest / C::NCH;
        int ci = ch * C::CK + kk;
        float v = (ci < CIN)
            ? W[(size_t)l * src_per + ((size_t)k * CIN + ci) * COUT + n] : 0.f;
        Wt[o] = __float2half_rn(v);
    }
}

template <int CIN, int COUT>
__global__ void __launch_bounds__(256)
spconv_mma(const __half* __restrict__ feat, int ldf,  // fp16 shadow input
           const int* __restrict__ nbr,
           const __half* __restrict__ Wt,             // packed fp16 weights
           const float* __restrict__ sb,
           const float* __restrict__ resid, int ldr,  // fp32
           const float* __restrict__ red,   int ldred,
           float* __restrict__ out, int ldo,
           __half* __restrict__ outs,                 // fp16 shadow out (or null)
           int N)
{
    using C = SpCfg<CIN, COUT>;
    constexpr int BM = C::BM, CK = C::CK, NCH = C::NCH;
    constexpr int SPH = C::SPH, SKW = C::SKW, VR = C::VR;
    constexpr int NT = C::NT, NP2 = C::NP2, KS = C::KS;

    extern __shared__ char smem_raw[];
    __half* sfeat = (__half*)smem_raw;                     // [2][BM*SPH]
    __half* sW    = sfeat + 2 * BM * SPH;                  // [2][COUT*SKW]
    int*    snbr  = (int*)(sW + 2 * COUT * SKW);           // [27*BM]
    int*    kmeta = snbr + 27 * BM;
    int*    khit  = kmeta;
    int*    klist = kmeta + 27;
    int*    knp   = kmeta + 54;

    const uint32_t sfeat_sa = (uint32_t)__cvta_generic_to_shared(sfeat);
    const uint32_t sW_sa    = (uint32_t)__cvta_generic_to_shared(sW);

    const int tid  = threadIdx.x;
    const int lane = tid & 31;
    const int wid  = tid >> 5;
    const int row0 = blockIdx.x * BM;

    // Stage neighbor indices
    for (int e = tid; e < BM * 27; e += 256) {
        int r = e / 27, k = e - r * 27;
        int g = row0 + r;
        snbr[k * BM + r] = (g < N) ? nbr[(size_t)g * 27 + k] : -1;
    }
    __syncthreads();
    if (tid < 27) {
        int h = 0;
        for (int r = 0; r < BM && !h; ++r) h = (snbr[tid * BM + r] >= 0);
        khit[tid] = h;
    }
    __syncthreads();
    if (tid == 0) {
        int n = 0;
        for (int k = 0; k < 27; ++k) if (khit[k]) klist[n++] = k;
        *knp = n;
    }
    __syncthreads();
    const int NS = (*knp) * NCH;

    float acc[NT][4];
#pragma unroll
    for (int t = 0; t < NT; ++t)
#pragma unroll
        for (int j = 0; j < 4; ++j) acc[t][j] = 0.f;

    auto stage = [&](int s) {
        const int k  = klist[s / NCH];
        const int ch = s - (s / NCH) * NCH;
        const int kb = s & 1;
        const uint32_t fb = sfeat_sa + (uint32_t)(kb * BM * SPH) * 2u;
        for (int u = tid; u < BM * VR; u += 256) {
            int r = u / VR, v = u - r * VR;
            int idx = snbr[k * BM + r];
            const __half* g = feat + (size_t)(idx < 0 ? 0 : idx) * ldf
                            + ch * CK + v * 8;
            cp_async16(fb + (uint32_t)(r * SPH + v * 8) * 2u, g, idx < 0 ? 0 : 16);
        }
        const __half* wg = Wt + (size_t)(k * NCH + ch) * COUT * CK;
        const uint32_t wb = sW_sa + (uint32_t)(kb * COUT * SKW) * 2u;
        for (int u = tid; u < COUT * CK / 8; u += 256) {
            int n = u / (CK / 8), c = u - n * (CK / 8);
            cp_async16(wb + (uint32_t)(n * SKW + c * 8) * 2u, wg + n * CK + c * 8, 16);
        }
    };

    const int mrow = wid * 16 + (lane >> 2);
    const int kq   = lane & 3;

    // ldmatrix per-thread address offsets (halves), hoisted out of the loop.
    const uint32_t a_off =
        (uint32_t)((wid * 16 + (lane & 7) + ((lane >> 3) & 1) * 8) * SPH
                   + (lane >> 4) * 8) * 2u;
    uint32_t b_off[NP2];
#pragma unroll
    for (int p = 0; p < NP2; ++p)
        b_off[p] = (uint32_t)(((p * 16 + ((lane >> 4) & 1) * 8 + (lane & 7)) * SKW)
                              + ((lane >> 3) & 1) * 8) * 2u;

    if (NS > 0) {
        stage(0);
        cp_commit();
        for (int s = 0; s < NS; ++s) {
            if (s + 1 < NS) { stage(s + 1); cp_commit(); cp_wait<1>(); }
            else            { cp_wait<0>(); }
            __syncthreads();

            const uint32_t fb = sfeat_sa + (uint32_t)((s & 1) * BM * SPH) * 2u;
            const uint32_t wb = sW_sa    + (uint32_t)((s & 1) * COUT * SKW) * 2u;
#pragma unroll
            for (int k16 = 0; k16 < KS; ++k16) {
                const uint32_t kco = (uint32_t)(k16 * 16) * 2u;
                uint32_t a0, a1, a2, a3;
                ldsm_x4(a0, a1, a2, a3, fb + a_off + kco);
#pragma unroll
                for (int p = 0; p < NP2; ++p) {
                    uint32_t b00, b01, b10, b11;
                    ldsm_x4(b00, b01, b10, b11, wb + b_off[p] + kco);
                    mma_fp16(acc[2 * p],     a0, a1, a2, a3, b00, b01);
                    mma_fp16(acc[2 * p + 1], a0, a1, a2, a3, b10, b11);
                }
            }
            __syncthreads();
        }
    }

    // -------- epilogue --------
    const int r0 = row0 + mrow;
#pragma unroll
    for (int t = 0; t < NT; ++t) {
        const int col = t * 8 + 2 * kq;
        const float s0 = sb[col],        s1 = sb[col + 1];
        const float b0 = sb[COUT + col], b1 = sb[COUT + col + 1];
#pragma unroll
        for (int h = 0; h < 2; ++h) {
            const int r = r0 + 8 * h;
            if (r >= N) continue;
            float v0 = acc[t][2 * h]     * s0 + b0;
            float v1 = acc[t][2 * h + 1] * s1 + b1;
            if (resid) {
                float2 rr = *(const float2*)(resid + (size_t)r * ldr + col);
                v0 += rr.x; v1 += rr.y;
            }
            v0 = fmaxf(v0, 0.f);
            v1 = fmaxf(v1, 0.f);
            if (red) {
                float4 ra = *(const float4*)(red + (size_t)r * ldred + 2 * col);
                v0 += ra.x + ra.y;
                v1 += ra.z + ra.w;
            }
            *(float2*)(out + (size_t)r * ldo + col) = make_float2(v0, v1);
            if (outs)
                *(__half2*)(outs + (size_t)r * ldo + col) =
                    __floats2half2_rn(v0, v1);
        }
    }
}

template <int CIN, int COUT>
static void conv_launch(const __half* feat, int ldf, const int* nbr,
                        const __half* Wt, const float* sb,
                        const float* resid, int ldr,
                        const float* red, int ldred,
                        float* out, int ldo, __half* outs, int N)
{
    constexpr int SM = SpCfg<CIN, COUT>::SMEM_BYTES;
    cudaFuncSetAttribute(spconv_mma<CIN, COUT>,
                         cudaFuncAttributeMaxDynamicSharedMemorySize, SM);
    const int grid = (N + 127) / 128;
    spconv_mma<CIN, COUT><<<grid, 256, SM>>>(
        feat, ldf, nbr, Wt, sb, resid, ldr, red, ldred, out, ldo, outs, N);
}

template <int CIN, int COUT>
static void pack_launch(const float* W, __half* Wt, int layers)
{
    constexpr int per = SpCfg<CIN, COUT>::PACKED_PER_LAYER;
    const int total = layers * per;
    pack_w_kernel<CIN, COUT><<<(total + 255) / 256, 256>>>(W, Wt, layers);
}

extern "C" void kernel_launch(void* const* d_in, const int* in_sizes, int n_in,
                              void* d_out, int out_size)
{
    const float* voxel  = (const float*)d_in[0];
    const float* Win    = (const float*)d_in[1];
    const float* W32    = (const float*)d_in[2];
    const float* W64    = (const float*)d_in[3];
    const float* Wd3    = (const float*)d_in[4];
    const float* W6432  = (const float*)d_in[5];
    const float* W12864 = (const float*)d_in[6];
    const float* bn32   = (const float*)d_in[7];
    const float* bn64   = (const float*)d_in[8];
    const int* nbr1  = (const int*)d_in[9];
    const int* nbr2  = (const int*)d_in[10];
    const int* nbr3  = (const int*)d_in[11];
    const int* nbr4  = (const int*)d_in[12];
    const int* nbrd2 = (const int*)d_in[13];
    const int* nbrd3 = (const int*)d_in[14];
    const int* nbrd4 = (const int*)d_in[15];
    const int* nbri4 = (const int*)d_in[16];
    const int* nbri3 = (const int*)d_in[17];
    const int* nbri2 = (const int*)d_in[18];

    const int N1 = in_sizes[9]  / 27;
    const int N2 = in_sizes[10] / 27;
    const int N3 = in_sizes[11] / 27;
    const int N4 = in_sizes[12] / 27;

    float* pool = nullptr;
    cudaGetSymbolAddress((void**)&pool, g_pool);

    size_t o = 0;   // float units
    auto takeF = [&](size_t n) { size_t r = o; o += (n + 255) & ~(size_t)255; return pool + r; };
    auto takeH = [&](size_t nh) { return (__half*)takeF((nh + 1) / 2); };

    // ---- packed fp16 weights ----
    constexpr int Pin    = SpCfg<4, 32>::PACKED_PER_LAYER;
    constexpr int P32    = SpCfg<32, 32>::PACKED_PER_LAYER;
    constexpr int P64    = SpCfg<64, 64>::PACKED_PER_LAYER;
    constexpr int Pd3    = SpCfg<32, 64>::PACKED_PER_LAYER;
    constexpr int P6432  = SpCfg<64, 32>::PACKED_PER_LAYER;
    constexpr int P12864 = SpCfg<128, 64>::PACKED_PER_LAYER;
    __half* pWin    = takeH(Pin);
    __half* pW32    = takeH((size_t)10 * P32);
    __half* pW64    = takeH((size_t)10 * P64);
    __half* pWd3    = takeH(Pd3);
    __half* pW6432  = takeH((size_t)3 * P6432);
    __half* pW12864 = takeH((size_t)2 * P12864);
    __half* voxs    = takeH((size_t)N1 * 16);     // zero-padded to 16 channels

    // ---- feature buffers: fp32 + fp16 shadow ----
    float *A, *X1, *cat1, *C, *Dm, *X2, *cat2, *Fm, *G, *X3, *cat3, *I, *J, *cat4;
    __half *As, *X1s, *cat1s, *Cs, *Dms, *X2s, *cat2s, *Fms, *Gs, *X3s, *cat3s,
           *Is, *Js, *cat4s;
    auto buf2 = [&](size_t n, float*& b, __half*& s) {
        b = takeF(n); s = takeH(n);
    };
    buf2((size_t)N1 * 32, A, As);
    buf2((size_t)N1 * 32, X1, X1s);
    buf2((size_t)N1 * 64, cat1, cat1s);
    buf2((size_t)N2 * 32, C, Cs);
    buf2((size_t)N2 * 32, Dm, Dms);
    buf2((size_t)N2 * 32, X2, X2s);
    buf2((size_t)N2 * 64, cat2, cat2s);
    buf2((size_t)N3 * 64, Fm, Fms);
    buf2((size_t)N3 * 64, G, Gs);
    buf2((size_t)N3 * 64, X3, X3s);
    buf2((size_t)N3 * 128, cat3, cat3s);
    buf2((size_t)N4 * 64, I, Is);
    buf2((size_t)N4 * 64, J, Js);
    buf2((size_t)N4 * 128, cat4, cat4s);

    float* outp = (float*)d_out;

    // ---- prologue: batched fp16 weight packing + padded voxel cvt ----
    pack_launch<4, 32>(Win, pWin, 1);
    pack_launch<32, 32>(W32, pW32, 10);
    pack_launch<64, 64>(W64, pW64, 10);
    pack_launch<32, 64>(Wd3, pWd3, 1);
    pack_launch<64, 32>(W6432, pW6432, 3);
    pack_launch<128, 64>(W12864, pW12864, 2);
    cvt_voxel_kernel<<<(N1 * 16 + 255) / 256, 256>>>(voxel, voxs, N1);

    // ---- Encoder ----
    conv_launch<4, 32>(voxs, 16, nbr1, pWin, bn32 + 0 * 64, nullptr, 0, nullptr, 0, A, 32, As, N1);
    conv_launch<32, 32>(As, 32, nbr1, pW32 + 0 * (size_t)P32, bn32 + 1 * 64, nullptr, 0, nullptr, 0, X1, 32, X1s, N1);
    conv_launch<32, 32>(X1s, 32, nbrd2, pW32 + 1 * (size_t)P32, bn32 + 2 * 64, nullptr, 0, nullptr, 0, C, 32, Cs, N2);
    conv_launch<32, 32>(Cs, 32, nbr2, pW32 + 2 * (size_t)P32, bn32 + 3 * 64, nullptr, 0, nullptr, 0, Dm, 32, Dms, N2);
    conv_launch<32, 32>(Dms, 32, nbr2, pW32 + 3 * (size_t)P32, bn32 + 4 * 64, nullptr, 0, nullptr, 0, X2, 32, X2s, N2);
    conv_launch<32, 64>(X2s, 32, nbrd3, pWd3, bn64 + 0 * 128, nullptr, 0, nullptr, 0, Fm, 64, Fms, N3);
    conv_launch<64, 64>(Fms, 64, nbr3, pW64 + 0 * (size_t)P64, bn64 + 1 * 128, nullptr, 0, nullptr, 0, G, 64, Gs, N3);
    conv_launch<64, 64>(Gs, 64, nbr3, pW64 + 1 * (size_t)P64, bn64 + 2 * 128, nullptr, 0, nullptr, 0, X3, 64, X3s, N3);
    conv_launch<64, 64>(X3s, 64, nbrd4, pW64 + 2 * (size_t)P64, bn64 + 3 * 128, nullptr, 0, nullptr, 0, I, 64, Is, N4);
    conv_launch<64, 64>(Is, 64, nbr4, pW64 + 3 * (size_t)P64, bn64 + 4 * 128, nullptr, 0, nullptr, 0, J, 64, Js, N4);
    conv_launch<64, 64>(Js, 64, nbr4, pW64 + 4 * (size_t)P64, bn64 + 5 * 128, nullptr, 0, nullptr, 0, cat4, 128, cat4s, N4);

    // ---- Bottleneck ----
    conv_launch<64, 64>(cat4s, 128, nbr4, pW64 + 5 * (size_t)P64, bn64 + 6 * 128, nullptr, 0, nullptr, 0, I, 64, Is, N4);
    conv_launch<64, 64>(Is, 64, nbr4, pW64 + 6 * (size_t)P64, bn64 + 7 * 128, cat4, 128, nullptr, 0, cat4 + 64, 128, cat4s + 64, N4);
    conv_launch<128, 64>(cat4s, 128, nbr4, pW12864 + 0 * (size_t)P12864, bn64 + 11 * 128, nullptr, 0, cat4, 128, J, 64, Js, N4);

    // ---- Decoder level 3 ----
    conv_launch<64, 64>(Js, 64, nbri4, pW64 + 7 * (size_t)P64, bn64 + 8 * 128, nullptr, 0, nullptr, 0, cat3, 128, cat3s, N3);
    conv_launch<64, 64>(X3s, 64, nbr3, pW64 + 8 * (size_t)P64, bn64 + 9 * 128, nullptr, 0, nullptr, 0, Fm, 64, Fms, N3);
    conv_launch<64, 64>(Fms, 64, nbr3, pW64 + 9 * (size_t)P64, bn64 + 10 * 128, X3, 64, nullptr, 0, cat3 + 64, 128, cat3s + 64, N3);
    conv_launch<128, 64>(cat3s, 128, nbr3, pW12864 + 1 * (size_t)P12864, bn64 + 12 * 128, nullptr, 0, cat3, 128, G, 64, Gs, N3);

    // ---- Decoder level 2 ----
    conv_launch<64, 32>(Gs, 64, nbri3, pW6432 + 0 * (size_t)P6432, bn32 + 11 * 64, nullptr, 0, nullptr, 0, cat2, 64, cat2s, N2);
    conv_launch<32, 32>(X2s, 32, nbr2, pW32 + 4 * (size_t)P32, bn32 + 5 * 64, nullptr, 0, nullptr, 0, C, 32, Cs, N2);
    conv_launch<32, 32>(Cs, 32, nbr2, pW32 + 5 * (size_t)P32, bn32 + 6 * 64, X2, 32, nullptr, 0, cat2 + 32, 64, cat2s + 32, N2);
    conv_launch<64, 32>(cat2s, 64, nbr2, pW6432 + 1 * (size_t)P6432, bn32 + 12 * 64, nullptr, 0, cat2, 64, Dm, 32, Dms, N2);

    // ---- Decoder level 1 ----
    conv_launch<32, 32>(Dms, 32, nbri2, pW32 + 6 * (size_t)P32, bn32 + 7 * 64, nullptr, 0, nullptr, 0, cat1, 64, cat1s, N1);
    conv_launch<32, 32>(X1s, 32, nbr1, pW32 + 7 * (size_t)P32, bn32 + 8 * 64, nullptr, 0, nullptr, 0, A, 32, As, N1);
    conv_launch<32, 32>(As, 32, nbr1, pW32 + 8 * (size_t)P32, bn32 + 9 * 64, X1, 32, nullptr, 0, cat1 + 32, 64, cat1s + 32, N1);
    conv_launch<64, 32>(cat1s, 64, nbr1, pW6432 + 2 * (size_t)P6432, bn32 + 13 * 64, nullptr, 0, cat1, 64, A, 32, As, N1);

    // ---- Head ----
    conv_launch<32, 32>(As, 32, nbr1, pW32 + 9 * (size_t)P32, bn32 + 10 * 64, nullptr, 0, nullptr, 0, outp, 32, nullptr, N1);
}

// round 16
// speedup vs baseline: 2.1323x; 1.0882x over previous
#include <cuda_runtime.h>
#include <cuda_fp16.h>
#include <cstddef>
#include <cstdint>

// ---------------------------------------------------------------------------
// Sparse 3D UNet forward.  fp16 mma.sync.m16n8k16 (fp32 accum) sparse conv.
// R16 = R15 + (a) two-stream execution: the decoder residual "t" branches run
// on a side stream forked (via events) right after their encoder inputs are
// ready, overlapping the main chain; (b) fp32 stores skipped for buffers only
// ever consumed through their fp16 shadow.
// ---------------------------------------------------------------------------

__device__ float g_pool[224u * 1024u * 1024u];   // 896 MB scratch (static: legal)

__device__ __forceinline__ void cp_async16(uint32_t dst, const void* src, int nbytes) {
    asm volatile("cp.async.cg.shared.global [%0], [%1], 16, %2;"
                 :: "r"(dst), "l"(src), "r"(nbytes));
}
__device__ __forceinline__ void cp_commit() {
    asm volatile("cp.async.commit_group;");
}
template <int NG> __device__ __forceinline__ void cp_wait() {
    asm volatile("cp.async.wait_group %0;" :: "n"(NG));
}
__device__ __forceinline__ void ldsm_x4(uint32_t& r0, uint32_t& r1,
                                        uint32_t& r2, uint32_t& r3, uint32_t addr) {
    asm volatile("ldmatrix.sync.aligned.m8n8.x4.shared.b16 {%0,%1,%2,%3}, [%4];"
                 : "=r"(r0), "=r"(r1), "=r"(r2), "=r"(r3) : "r"(addr));
}
__device__ __forceinline__ void mma_fp16(float c[4], uint32_t a0, uint32_t a1,
                                         uint32_t a2, uint32_t a3,
                                         uint32_t b0, uint32_t b1) {
    asm volatile(
        "mma.sync.aligned.m16n8k16.row.col.f32.f16.f16.f32 "
        "{%0,%1,%2,%3},{%4,%5,%6,%7},{%8,%9},{%0,%1,%2,%3};"
        : "+f"(c[0]), "+f"(c[1]), "+f"(c[2]), "+f"(c[3])
        : "r"(a0), "r"(a1), "r"(a2), "r"(a3), "r"(b0), "r"(b1));
}

// voxel fp32 [N][4] -> fp16 [N][16] zero-padded
__global__ void cvt_voxel_kernel(const float* __restrict__ in,
                                 __half* __restrict__ out, int n) {
    for (int i = blockIdx.x * blockDim.x + threadIdx.x; i < n * 16;
         i += gridDim.x * blockDim.x) {
        int r = i >> 4, c = i & 15;
        out[i] = (c < 4) ? __float2half_rn(in[r * 4 + c]) : __half(0.f);
    }
}

template <int CIN, int COUT>
struct SpCfg {
    static constexpr int BM  = 128;
    static constexpr int CK  = (CIN < 32) ? 16 : ((CIN >= 64) ? 64 : 32);
    static constexpr int NCH = (CIN + CK - 1) / CK;
    static constexpr int SPH = CK + 8;                  // feat row stride (halves)
    static constexpr int SKW = CK + 8;                  // W row stride (halves)
    static constexpr int VR  = CK / 8;                  // 16B vecs per feat row
    static constexpr int NT  = COUT / 8;                // n-tiles (4 or 8)
    static constexpr int NP2 = NT / 2;                  // n-tile pairs
    static constexpr int KS  = CK / 16;                 // k16 steps per stage
    static constexpr int SMEM_BYTES =
        (2 * BM * SPH + 2 * COUT * SKW) * 2 + 27 * BM * 4 + 64 * 4;
    static constexpr int PACKED_PER_LAYER = 27 * NCH * COUT * CK;   // halves
};

// Pack W fp32 (L,27,CIN,COUT) -> fp16 transposed [l][k][ch][n][kk], zero pad.
template <int CIN, int COUT>
__global__ void pack_w_kernel(const float* __restrict__ W, __half* __restrict__ Wt,
                              int layers) {
    using C = SpCfg<CIN, COUT>;
    const int per = C::PACKED_PER_LAYER;
    const int total = layers * per;
    const size_t src_per = 27u * CIN * COUT;
    for (int o = blockIdx.x * blockDim.x + threadIdx.x; o < total;
         o += gridDim.x * blockDim.x) {
        int l = o / per;
        int q = o - l * per;
        int kk = q % C::CK;
        int rest = q / C::CK;
        int n  = rest % COUT; rest /= COUT;
        int ch = rest % C::NCH;
        int k  = rest / C::NCH;
        int ci = ch * C::CK + kk;
        float v = (ci < CIN)
            ? W[(size_t)l * src_per + ((size_t)k * CIN + ci) * COUT + n] : 0.f;
        Wt[o] = __float2half_rn(v);
    }
}

template <int CIN, int COUT>
__global__ void __launch_bounds__(256)
spconv_mma(const __half* __restrict__ feat, int ldf,  // fp16 shadow input
           const int* __restrict__ nbr,
           const __half* __restrict__ Wt,             // packed fp16 weights
           const float* __restrict__ sb,
           const float* __restrict__ resid, int ldr,  // fp32
           const float* __restrict__ red,   int ldred,
           float* __restrict__ out, int ldo,          // fp32 out (or null)
           __half* __restrict__ outs,                 // fp16 shadow out (or null)
           int N)
{
    using C = SpCfg<CIN, COUT>;
    constexpr int BM = C::BM, CK = C::CK, NCH = C::NCH;
    constexpr int SPH = C::SPH, SKW = C::SKW, VR = C::VR;
    constexpr int NT = C::NT, NP2 = C::NP2, KS = C::KS;

    extern __shared__ char smem_raw[];
    __half* sfeat = (__half*)smem_raw;                     // [2][BM*SPH]
    __half* sW    = sfeat + 2 * BM * SPH;                  // [2][COUT*SKW]
    int*    snbr  = (int*)(sW + 2 * COUT * SKW);           // [27*BM]
    int*    kmeta = snbr + 27 * BM;
    int*    khit  = kmeta;
    int*    klist = kmeta + 27;
    int*    knp   = kmeta + 54;

    const uint32_t sfeat_sa = (uint32_t)__cvta_generic_to_shared(sfeat);
    const uint32_t sW_sa    = (uint32_t)__cvta_generic_to_shared(sW);

    const int tid  = threadIdx.x;
    const int lane = tid & 31;
    const int wid  = tid >> 5;
    const int row0 = blockIdx.x * BM;

    // Stage neighbor indices
    for (int e = tid; e < BM * 27; e += 256) {
        int r = e / 27, k = e - r * 27;
        int g = row0 + r;
        snbr[k * BM + r] = (g < N) ? nbr[(size_t)g * 27 + k] : -1;
    }
    __syncthreads();
    if (tid < 27) {
        int h = 0;
        for (int r = 0; r < BM && !h; ++r) h = (snbr[tid * BM + r] >= 0);
        khit[tid] = h;
    }
    __syncthreads();
    if (tid == 0) {
        int n = 0;
        for (int k = 0; k < 27; ++k) if (khit[k]) klist[n++] = k;
        *knp = n;
    }
    __syncthreads();
    const int NS = (*knp) * NCH;

    float acc[NT][4];
#pragma unroll
    for (int t = 0; t < NT; ++t)
#pragma unroll
        for (int j = 0; j < 4; ++j) acc[t][j] = 0.f;

    auto stage = [&](int s) {
        const int k  = klist[s / NCH];
        const int ch = s - (s / NCH) * NCH;
        const int kb = s & 1;
        const uint32_t fb = sfeat_sa + (uint32_t)(kb * BM * SPH) * 2u;
        for (int u = tid; u < BM * VR; u += 256) {
            int r = u / VR, v = u - r * VR;
            int idx = snbr[k * BM + r];
            const __half* g = feat + (size_t)(idx < 0 ? 0 : idx) * ldf
                            + ch * CK + v * 8;
            cp_async16(fb + (uint32_t)(r * SPH + v * 8) * 2u, g, idx < 0 ? 0 : 16);
        }
        const __half* wg = Wt + (size_t)(k * NCH + ch) * COUT * CK;
        const uint32_t wb = sW_sa + (uint32_t)(kb * COUT * SKW) * 2u;
        for (int u = tid; u < COUT * CK / 8; u += 256) {
            int n = u / (CK / 8), c = u - n * (CK / 8);
            cp_async16(wb + (uint32_t)(n * SKW + c * 8) * 2u, wg + n * CK + c * 8, 16);
        }
    };

    const int mrow = wid * 16 + (lane >> 2);
    const int kq   = lane & 3;

    const uint32_t a_off =
        (uint32_t)((wid * 16 + (lane & 7) + ((lane >> 3) & 1) * 8) * SPH
                   + (lane >> 4) * 8) * 2u;
    uint32_t b_off[NP2];
#pragma unroll
    for (int p = 0; p < NP2; ++p)
        b_off[p] = (uint32_t)(((p * 16 + ((lane >> 4) & 1) * 8 + (lane & 7)) * SKW)
                              + ((lane >> 3) & 1) * 8) * 2u;

    if (NS > 0) {
        stage(0);
        cp_commit();
        for (int s = 0; s < NS; ++s) {
            if (s + 1 < NS) { stage(s + 1); cp_commit(); cp_wait<1>(); }
            else            { cp_wait<0>(); }
            __syncthreads();

            const uint32_t fb = sfeat_sa + (uint32_t)((s & 1) * BM * SPH) * 2u;
            const uint32_t wb = sW_sa    + (uint32_t)((s & 1) * COUT * SKW) * 2u;
#pragma unroll
            for (int k16 = 0; k16 < KS; ++k16) {
                const uint32_t kco = (uint32_t)(k16 * 16) * 2u;
                uint32_t a0, a1, a2, a3;
                ldsm_x4(a0, a1, a2, a3, fb + a_off + kco);
#pragma unroll
                for (int p = 0; p < NP2; ++p) {
                    uint32_t b00, b01, b10, b11;
                    ldsm_x4(b00, b01, b10, b11, wb + b_off[p] + kco);
                    mma_fp16(acc[2 * p],     a0, a1, a2, a3, b00, b01);
                    mma_fp16(acc[2 * p + 1], a0, a1, a2, a3, b10, b11);
                }
            }
            __syncthreads();
        }
    }

    // -------- epilogue --------
    const int r0 = row0 + mrow;
#pragma unroll
    for (int t = 0; t < NT; ++t) {
        const int col = t * 8 + 2 * kq;
        const float s0 = sb[col],        s1 = sb[col + 1];
        const float b0 = sb[COUT + col], b1 = sb[COUT + col + 1];
#pragma unroll
        for (int h = 0; h < 2; ++h) {
            const int r = r0 + 8 * h;
            if (r >= N) continue;
            float v0 = acc[t][2 * h]     * s0 + b0;
            float v1 = acc[t][2 * h + 1] * s1 + b1;
            if (resid) {
                float2 rr = *(const float2*)(resid + (size_t)r * ldr + col);
                v0 += rr.x; v1 += rr.y;
            }
            v0 = fmaxf(v0, 0.f);
            v1 = fmaxf(v1, 0.f);
            if (red) {
                float4 ra = *(const float4*)(red + (size_t)r * ldred + 2 * col);
                v0 += ra.x + ra.y;
                v1 += ra.z + ra.w;
            }
            if (out)
                *(float2*)(out + (size_t)r * ldo + col) = make_float2(v0, v1);
            if (outs)
                *(__half2*)(outs + (size_t)r * ldo + col) =
                    __floats2half2_rn(v0, v1);
        }
    }
}

template <int CIN, int COUT>
static void conv_launch(cudaStream_t st,
                        const __half* feat, int ldf, const int* nbr,
                        const __half* Wt, const float* sb,
                        const float* resid, int ldr,
                        const float* red, int ldred,
                        float* out, int ldo, __half* outs, int N)
{
    constexpr int SM = SpCfg<CIN, COUT>::SMEM_BYTES;
    cudaFuncSetAttribute(spconv_mma<CIN, COUT>,
                         cudaFuncAttributeMaxDynamicSharedMemorySize, SM);
    const int grid = (N + 127) / 128;
    spconv_mma<CIN, COUT><<<grid, 256, SM, st>>>(
        feat, ldf, nbr, Wt, sb, resid, ldr, red, ldred, out, ldo, outs, N);
}

template <int CIN, int COUT>
static void pack_launch(const float* W, __half* Wt, int layers)
{
    constexpr int per = SpCfg<CIN, COUT>::PACKED_PER_LAYER;
    const int total = layers * per;
    pack_w_kernel<CIN, COUT><<<(total + 255) / 256, 256>>>(W, Wt, layers);
}

extern "C" void kernel_launch(void* const* d_in, const int* in_sizes, int n_in,
                              void* d_out, int out_size)
{
    const float* voxel  = (const float*)d_in[0];
    const float* Win    = (const float*)d_in[1];
    const float* W32    = (const float*)d_in[2];
    const float* W64    = (const float*)d_in[3];
    const float* Wd3    = (const float*)d_in[4];
    const float* W6432  = (const float*)d_in[5];
    const float* W12864 = (const float*)d_in[6];
    const float* bn32   = (const float*)d_in[7];
    const float* bn64   = (const float*)d_in[8];
    const int* nbr1  = (const int*)d_in[9];
    const int* nbr2  = (const int*)d_in[10];
    const int* nbr3  = (const int*)d_in[11];
    const int* nbr4  = (const int*)d_in[12];
    const int* nbrd2 = (const int*)d_in[13];
    const int* nbrd3 = (const int*)d_in[14];
    const int* nbrd4 = (const int*)d_in[15];
    const int* nbri4 = (const int*)d_in[16];
    const int* nbri3 = (const int*)d_in[17];
    const int* nbri2 = (const int*)d_in[18];

    const int N1 = in_sizes[9]  / 27;
    const int N2 = in_sizes[10] / 27;
    const int N3 = in_sizes[11] / 27;
    const int N4 = in_sizes[12] / 27;

    // One-time stream/event setup (host resources, not device memory).
    static cudaStream_t s1 = nullptr;
    static cudaEvent_t evx1, evx2, evx3, evd1, evd2, evd3;
    if (!s1) {
        cudaStreamCreateWithFlags(&s1, cudaStreamNonBlocking);
        cudaEventCreateWithFlags(&evx1, cudaEventDisableTiming);
        cudaEventCreateWithFlags(&evx2, cudaEventDisableTiming);
        cudaEventCreateWithFlags(&evx3, cudaEventDisableTiming);
        cudaEventCreateWithFlags(&evd1, cudaEventDisableTiming);
        cudaEventCreateWithFlags(&evd2, cudaEventDisableTiming);
        cudaEventCreateWithFlags(&evd3, cudaEventDisableTiming);
    }
    const cudaStream_t s0 = 0;   // legacy (captured) stream

    float* pool = nullptr;
    cudaGetSymbolAddress((void**)&pool, g_pool);

    size_t o = 0;   // float units
    auto takeF = [&](size_t n) { size_t r = o; o += (n + 255) & ~(size_t)255; return pool + r; };
    auto takeH = [&](size_t nh) { return (__half*)takeF((nh + 1) / 2); };

    // ---- packed fp16 weights ----
    constexpr int Pin    = SpCfg<4, 32>::PACKED_PER_LAYER;
    constexpr int P32    = SpCfg<32, 32>::PACKED_PER_LAYER;
    constexpr int P64    = SpCfg<64, 64>::PACKED_PER_LAYER;
    constexpr int Pd3    = SpCfg<32, 64>::PACKED_PER_LAYER;
    constexpr int P6432  = SpCfg<64, 32>::PACKED_PER_LAYER;
    constexpr int P12864 = SpCfg<128, 64>::PACKED_PER_LAYER;
    __half* pWin    = takeH(Pin);
    __half* pW32    = takeH((size_t)10 * P32);
    __half* pW64    = takeH((size_t)10 * P64);
    __half* pWd3    = takeH(Pd3);
    __half* pW6432  = takeH((size_t)3 * P6432);
    __half* pW12864 = takeH((size_t)2 * P12864);
    __half* voxs    = takeH((size_t)N1 * 16);

    // ---- feature buffers: fp32 + fp16 shadow ----
    float *A, *X1, *cat1, *C, *Dm, *X2, *cat2, *Fm, *G, *X3, *cat3, *I, *J, *cat4, *T1;
    __half *As, *X1s, *cat1s, *Cs, *Dms, *X2s, *cat2s, *Fms, *Gs, *X3s, *cat3s,
           *Is, *Js, *cat4s, *T1s;
    auto buf2 = [&](size_t n, float*& b, __half*& s) {
        b = takeF(n); s = takeH(n);
    };
    buf2((size_t)N1 * 32, A, As);
    buf2((size_t)N1 * 32, X1, X1s);
    buf2((size_t)N1 * 64, cat1, cat1s);
    buf2((size_t)N1 * 32, T1, T1s);          // dedicated temp for dec1 t-branch
    buf2((size_t)N2 * 32, C, Cs);
    buf2((size_t)N2 * 32, Dm, Dms);
    buf2((size_t)N2 * 32, X2, X2s);
    buf2((size_t)N2 * 64, cat2, cat2s);
    buf2((size_t)N3 * 64, Fm, Fms);
    buf2((size_t)N3 * 64, G, Gs);
    buf2((size_t)N3 * 64, X3, X3s);
    buf2((size_t)N3 * 128, cat3, cat3s);
    buf2((size_t)N4 * 64, I, Is);
    buf2((size_t)N4 * 64, J, Js);
    buf2((size_t)N4 * 128, cat4, cat4s);

    float* outp = (float*)d_out;

    // ---- prologue (main stream) ----
    pack_launch<4, 32>(Win, pWin, 1);
    pack_launch<32, 32>(W32, pW32, 10);
    pack_launch<64, 64>(W64, pW64, 10);
    pack_launch<32, 64>(Wd3, pWd3, 1);
    pack_launch<64, 32>(W6432, pW6432, 3);
    pack_launch<128, 64>(W12864, pW12864, 2);
    cvt_voxel_kernel<<<(N1 * 16 + 255) / 256, 256>>>(voxel, voxs, N1);

    // ---- Encoder (main) ----
    conv_launch<4, 32>(s0, voxs, 16, nbr1, pWin, bn32 + 0 * 64, nullptr, 0, nullptr, 0, nullptr, 32, As, N1);
    conv_launch<32, 32>(s0, As, 32, nbr1, pW32 + 0 * (size_t)P32, bn32 + 1 * 64, nullptr, 0, nullptr, 0, X1, 32, X1s, N1);
    cudaEventRecord(evx1, s0);
    conv_launch<32, 32>(s0, X1s, 32, nbrd2, pW32 + 1 * (size_t)P32, bn32 + 2 * 64, nullptr, 0, nullptr, 0, nullptr, 32, Cs, N2);
    conv_launch<32, 32>(s0, Cs, 32, nbr2, pW32 + 2 * (size_t)P32, bn32 + 3 * 64, nullptr, 0, nullptr, 0, nullptr, 32, Dms, N2);
    conv_launch<32, 32>(s0, Dms, 32, nbr2, pW32 + 3 * (size_t)P32, bn32 + 4 * 64, nullptr, 0, nullptr, 0, X2, 32, X2s, N2);
    cudaEventRecord(evx2, s0);
    conv_launch<32, 64>(s0, X2s, 32, nbrd3, pWd3, bn64 + 0 * 128, nullptr, 0, nullptr, 0, nullptr, 64, Fms, N3);
    conv_launch<64, 64>(s0, Fms, 64, nbr3, pW64 + 0 * (size_t)P64, bn64 + 1 * 128, nullptr, 0, nullptr, 0, nullptr, 64, Gs, N3);
    conv_launch<64, 64>(s0, Gs, 64, nbr3, pW64 + 1 * (size_t)P64, bn64 + 2 * 128, nullptr, 0, nullptr, 0, X3, 64, X3s, N3);
    cudaEventRecord(evx3, s0);

    // ---- Side stream: decoder t-branches (forked off encoder outputs) ----
    cudaStreamWaitEvent(s1, evx1, 0);
    conv_launch<32, 32>(s1, X1s, 32, nbr1, pW32 + 7 * (size_t)P32, bn32 + 8 * 64, nullptr, 0, nullptr, 0, nullptr, 32, T1s, N1);
    conv_launch<32, 32>(s1, T1s, 32, nbr1, pW32 + 8 * (size_t)P32, bn32 + 9 * 64, X1, 32, nullptr, 0, cat1 + 32, 64, cat1s + 32, N1);
    cudaEventRecord(evd1, s1);
    cudaStreamWaitEvent(s1, evx2, 0);
    conv_launch<32, 32>(s1, X2s, 32, nbr2, pW32 + 4 * (size_t)P32, bn32 + 5 * 64, nullptr, 0, nullptr, 0, nullptr, 32, Cs, N2);
    conv_launch<32, 32>(s1, Cs, 32, nbr2, pW32 + 5 * (size_t)P32, bn32 + 6 * 64, X2, 32, nullptr, 0, cat2 + 32, 64, cat2s + 32, N2);
    cudaEventRecord(evd2, s1);
    cudaStreamWaitEvent(s1, evx3, 0);
    conv_launch<64, 64>(s1, X3s, 64, nbr3, pW64 + 8 * (size_t)P64, bn64 + 9 * 128, nullptr, 0, nullptr, 0, nullptr, 64, Fms, N3);
    conv_launch<64, 64>(s1, Fms, 64, nbr3, pW64 + 9 * (size_t)P64, bn64 + 10 * 128, X3, 64, nullptr, 0, cat3 + 64, 128, cat3s + 64, N3);
    cudaEventRecord(evd3, s1);

    // ---- Main: encoder tail + bottleneck ----
    conv_launch<64, 64>(s0, X3s, 64, nbrd4, pW64 + 2 * (size_t)P64, bn64 + 3 * 128, nullptr, 0, nullptr, 0, nullptr, 64, Is, N4);
    conv_launch<64, 64>(s0, Is, 64, nbr4, pW64 + 3 * (size_t)P64, bn64 + 4 * 128, nullptr, 0, nullptr, 0, nullptr, 64, Js, N4);
    conv_launch<64, 64>(s0, Js, 64, nbr4, pW64 + 4 * (size_t)P64, bn64 + 5 * 128, nullptr, 0, nullptr, 0, cat4, 128, cat4s, N4);
    conv_launch<64, 64>(s0, cat4s, 128, nbr4, pW64 + 5 * (size_t)P64, bn64 + 6 * 128, nullptr, 0, nullptr, 0, nullptr, 64, Is, N4);
    conv_launch<64, 64>(s0, Is, 64, nbr4, pW64 + 6 * (size_t)P64, bn64 + 7 * 128, cat4, 128, nullptr, 0, cat4 + 64, 128, cat4s + 64, N4);
    conv_launch<128, 64>(s0, cat4s, 128, nbr4, pW12864 + 0 * (size_t)P12864, bn64 + 11 * 128, nullptr, 0, cat4, 128, nullptr, 64, Js, N4);

    // ---- Decoder level 3 ----
    conv_launch<64, 64>(s0, Js, 64, nbri4, pW64 + 7 * (size_t)P64, bn64 + 8 * 128, nullptr, 0, nullptr, 0, cat3, 128, cat3s, N3);
    cudaStreamWaitEvent(s0, evd3, 0);
    conv_launch<128, 64>(s0, cat3s, 128, nbr3, pW12864 + 1 * (size_t)P12864, bn64 + 12 * 128, nullptr, 0, cat3, 128, nullptr, 64, Gs, N3);

    // ---- Decoder level 2 ----
    conv_launch<64, 32>(s0, Gs, 64, nbri3, pW6432 + 0 * (size_t)P6432, bn32 + 11 * 64, nullptr, 0, nullptr, 0, cat2, 64, cat2s, N2);
    cudaStreamWaitEvent(s0, evd2, 0);
    conv_launch<64, 32>(s0, cat2s, 64, nbr2, pW6432 + 1 * (size_t)P6432, bn32 + 12 * 64, nullptr, 0, cat2, 64, nullptr, 32, Dms, N2);

    // ---- Decoder level 1 ----
    conv_launch<32, 32>(s0, Dms, 32, nbri2, pW32 + 6 * (size_t)P32, bn32 + 7 * 64, nullptr, 0, nullptr, 0, cat1, 64, cat1s, N1);
    cudaStreamWaitEvent(s0, evd1, 0);
    conv_launch<64, 32>(s0, cat1s, 64, nbr1, pW6432 + 2 * (size_t)P6432, bn32 + 13 * 64, nullptr, 0, cat1, 64, nullptr, 32, As, N1);

    // ---- Head ----
    conv_launch<32, 32>(s0, As, 32, nbr1, pW32 + 9 * (size_t)P32, bn32 + 10 * 64, nullptr, 0, nullptr, 0, outp, 32, nullptr, N1);
}

// round 17
// speedup vs baseline: 2.1343x; 1.0009x over previous
#include <cuda_runtime.h>
#include <cuda_fp16.h>
#include <cstddef>
#include <cstdint>

// ---------------------------------------------------------------------------
// Sparse 3D UNet forward.  fp16 mma.sync.m16n8k16 (fp32 accum) sparse conv.
// R16 = R15 + (a) two-stream execution: the decoder residual "t" branches run
// on a side stream forked (via events) right after their encoder inputs are
// ready, overlapping the main chain; (b) fp32 stores skipped for buffers only
// ever consumed through their fp16 shadow.
// ---------------------------------------------------------------------------

__device__ float g_pool[224u * 1024u * 1024u];   // 896 MB scratch (static: legal)

__device__ __forceinline__ void cp_async16(uint32_t dst, const void* src, int nbytes) {
    asm volatile("cp.async.cg.shared.global [%0], [%1], 16, %2;"
                 :: "r"(dst), "l"(src), "r"(nbytes));
}
__device__ __forceinline__ void cp_commit() {
    asm volatile("cp.async.commit_group;");
}
template <int NG> __device__ __forceinline__ void cp_wait() {
    asm volatile("cp.async.wait_group %0;" :: "n"(NG));
}
__device__ __forceinline__ void ldsm_x4(uint32_t& r0, uint32_t& r1,
                                        uint32_t& r2, uint32_t& r3, uint32_t addr) {
    asm volatile("ldmatrix.sync.aligned.m8n8.x4.shared.b16 {%0,%1,%2,%3}, [%4];"
                 : "=r"(r0), "=r"(r1), "=r"(r2), "=r"(r3) : "r"(addr));
}
__device__ __forceinline__ void mma_fp16(float c[4], uint32_t a0, uint32_t a1,
                                         uint32_t a2, uint32_t a3,
                                         uint32_t b0, uint32_t b1) {
    asm volatile(
        "mma.sync.aligned.m16n8k16.row.col.f32.f16.f16.f32 "
        "{%0,%1,%2,%3},{%4,%5,%6,%7},{%8,%9},{%0,%1,%2,%3};"
        : "+f"(c[0]), "+f"(c[1]), "+f"(c[2]), "+f"(c[3])
        : "r"(a0), "r"(a1), "r"(a2), "r"(a3), "r"(b0), "r"(b1));
}

// voxel fp32 [N][4] -> fp16 [N][16] zero-padded
__global__ void cvt_voxel_kernel(const float* __restrict__ in,
                                 __half* __restrict__ out, int n) {
    for (int i = blockIdx.x * blockDim.x + threadIdx.x; i < n * 16;
         i += gridDim.x * blockDim.x) {
        int r = i >> 4, c = i & 15;
        out[i] = (c < 4) ? __float2half_rn(in[r * 4 + c]) : __half(0.f);
    }
}

template <int CIN, int COUT>
struct SpCfg {
    static constexpr int BM  = 128;
    static constexpr int CK  = (CIN < 32) ? 16 : ((CIN >= 64) ? 64 : 32);
    static constexpr int NCH = (CIN + CK - 1) / CK;
    static constexpr int SPH = CK + 8;                  // feat row stride (halves)
    static constexpr int SKW = CK + 8;                  // W row stride (halves)
    static constexpr int VR  = CK / 8;                  // 16B vecs per feat row
    static constexpr int NT  = COUT / 8;                // n-tiles (4 or 8)
    static constexpr int NP2 = NT / 2;                  // n-tile pairs
    static constexpr int KS  = CK / 16;                 // k16 steps per stage
    static constexpr int SMEM_BYTES =
        (2 * BM * SPH + 2 * COUT * SKW) * 2 + 27 * BM * 4 + 64 * 4;
    static constexpr int PACKED_PER_LAYER = 27 * NCH * COUT * CK;   // halves
};

// Pack W fp32 (L,27,CIN,COUT) -> fp16 transposed [l][k][ch][n][kk], zero pad.
template <int CIN, int COUT>
__global__ void pack_w_kernel(const float* __restrict__ W, __half* __restrict__ Wt,
                              int layers) {
    using C = SpCfg<CIN, COUT>;
    const int per = C::PACKED_PER_LAYER;
    const int total = layers * per;
    const size_t src_per = 27u * CIN * COUT;
    for (int o = blockIdx.x * blockDim.x + threadIdx.x; o < total;
         o += gridDim.x * blockDim.x) {
        int l = o / per;
        int q = o - l * per;
        int kk = q % C::CK;
        int rest = q / C::CK;
        int n  = rest % COUT; rest /= COUT;
        int ch = rest % C::NCH;
        int k  = rest / C::NCH;
        int ci = ch * C::CK + kk;
        float v = (ci < CIN)
            ? W[(size_t)l * src_per + ((size_t)k * CIN + ci) * COUT + n] : 0.f;
        Wt[o] = __float2half_rn(v);
    }
}

template <int CIN, int COUT>
__global__ void __launch_bounds__(256)
spconv_mma(const __half* __restrict__ feat, int ldf,  // fp16 shadow input
           const int* __restrict__ nbr,
           const __half* __restrict__ Wt,             // packed fp16 weights
           const float* __restrict__ sb,
           const float* __restrict__ resid, int ldr,  // fp32
           const float* __restrict__ red,   int ldred,
           float* __restrict__ out, int ldo,          // fp32 out (or null)
           __half* __restrict__ outs,                 // fp16 shadow out (or null)
           int N)
{
    using C = SpCfg<CIN, COUT>;
    constexpr int BM = C::BM, CK = C::CK, NCH = C::NCH;
    constexpr int SPH = C::SPH, SKW = C::SKW, VR = C::VR;
    constexpr int NT = C::NT, NP2 = C::NP2, KS = C::KS;

    extern __shared__ char smem_raw[];
    __half* sfeat = (__half*)smem_raw;                     // [2][BM*SPH]
    __half* sW    = sfeat + 2 * BM * SPH;                  // [2][COUT*SKW]
    int*    snbr  = (int*)(sW + 2 * COUT * SKW);           // [27*BM]
    int*    kmeta = snbr + 27 * BM;
    int*    khit  = kmeta;
    int*    klist = kmeta + 27;
    int*    knp   = kmeta + 54;

    const uint32_t sfeat_sa = (uint32_t)__cvta_generic_to_shared(sfeat);
    const uint32_t sW_sa    = (uint32_t)__cvta_generic_to_shared(sW);

    const int tid  = threadIdx.x;
    const int lane = tid & 31;
    const int wid  = tid >> 5;
    const int row0 = blockIdx.x * BM;

    // Stage neighbor indices
    for (int e = tid; e < BM * 27; e += 256) {
        int r = e / 27, k = e - r * 27;
        int g = row0 + r;
        snbr[k * BM + r] = (g < N) ? nbr[(size_t)g * 27 + k] : -1;
    }
    __syncthreads();
    if (tid < 27) {
        int h = 0;
        for (int r = 0; r < BM && !h; ++r) h = (snbr[tid * BM + r] >= 0);
        khit[tid] = h;
    }
    __syncthreads();
    if (tid == 0) {
        int n = 0;
        for (int k = 0; k < 27; ++k) if (khit[k]) klist[n++] = k;
        *knp = n;
    }
    __syncthreads();
    const int NS = (*knp) * NCH;

    float acc[NT][4];
#pragma unroll
    for (int t = 0; t < NT; ++t)
#pragma unroll
        for (int j = 0; j < 4; ++j) acc[t][j] = 0.f;

    auto stage = [&](int s) {
        const int k  = klist[s / NCH];
        const int ch = s - (s / NCH) * NCH;
        const int kb = s & 1;
        const uint32_t fb = sfeat_sa + (uint32_t)(kb * BM * SPH) * 2u;
        for (int u = tid; u < BM * VR; u += 256) {
            int r = u / VR, v = u - r * VR;
            int idx = snbr[k * BM + r];
            const __half* g = feat + (size_t)(idx < 0 ? 0 : idx) * ldf
                            + ch * CK + v * 8;
            cp_async16(fb + (uint32_t)(r * SPH + v * 8) * 2u, g, idx < 0 ? 0 : 16);
        }
        const __half* wg = Wt + (size_t)(k * NCH + ch) * COUT * CK;
        const uint32_t wb = sW_sa + (uint32_t)(kb * COUT * SKW) * 2u;
        for (int u = tid; u < COUT * CK / 8; u += 256) {
            int n = u / (CK / 8), c = u - n * (CK / 8);
            cp_async16(wb + (uint32_t)(n * SKW + c * 8) * 2u, wg + n * CK + c * 8, 16);
        }
    };

    const int mrow = wid * 16 + (lane >> 2);
    const int kq   = lane & 3;

    const uint32_t a_off =
        (uint32_t)((wid * 16 + (lane & 7) + ((lane >> 3) & 1) * 8) * SPH
                   + (lane >> 4) * 8) * 2u;
    uint32_t b_off[NP2];
#pragma unroll
    for (int p = 0; p < NP2; ++p)
        b_off[p] = (uint32_t)(((p * 16 + ((lane >> 4) & 1) * 8 + (lane & 7)) * SKW)
                              + ((lane >> 3) & 1) * 8) * 2u;

    if (NS > 0) {
        stage(0);
        cp_commit();
        for (int s = 0; s < NS; ++s) {
            if (s + 1 < NS) { stage(s + 1); cp_commit(); cp_wait<1>(); }
            else            { cp_wait<0>(); }
            __syncthreads();

            const uint32_t fb = sfeat_sa + (uint32_t)((s & 1) * BM * SPH) * 2u;
            const uint32_t wb = sW_sa    + (uint32_t)((s & 1) * COUT * SKW) * 2u;
#pragma unroll
            for (int k16 = 0; k16 < KS; ++k16) {
                const uint32_t kco = (uint32_t)(k16 * 16) * 2u;
                uint32_t a0, a1, a2, a3;
                ldsm_x4(a0, a1, a2, a3, fb + a_off + kco);
#pragma unroll
                for (int p = 0; p < NP2; ++p) {
                    uint32_t b00, b01, b10, b11;
                    ldsm_x4(b00, b01, b10, b11, wb + b_off[p] + kco);
                    mma_fp16(acc[2 * p],     a0, a1, a2, a3, b00, b01);
                    mma_fp16(acc[2 * p + 1], a0, a1, a2, a3, b10, b11);
                }
            }
            __syncthreads();
        }
    }

    // -------- epilogue --------
    const int r0 = row0 + mrow;
#pragma unroll
    for (int t = 0; t < NT; ++t) {
        const int col = t * 8 + 2 * kq;
        const float s0 = sb[col],        s1 = sb[col + 1];
        const float b0 = sb[COUT + col], b1 = sb[COUT + col + 1];
#pragma unroll
        for (int h = 0; h < 2; ++h) {
            const int r = r0 + 8 * h;
            if (r >= N) continue;
            float v0 = acc[t][2 * h]     * s0 + b0;
            float v1 = acc[t][2 * h + 1] * s1 + b1;
            if (resid) {
                float2 rr = *(const float2*)(resid + (size_t)r * ldr + col);
                v0 += rr.x; v1 += rr.y;
            }
            v0 = fmaxf(v0, 0.f);
            v1 = fmaxf(v1, 0.f);
            if (red) {
                float4 ra = *(const float4*)(red + (size_t)r * ldred + 2 * col);
                v0 += ra.x + ra.y;
                v1 += ra.z + ra.w;
            }
            if (out)
                *(float2*)(out + (size_t)r * ldo + col) = make_float2(v0, v1);
            if (outs)
                *(__half2*)(outs + (size_t)r * ldo + col) =
                    __floats2half2_rn(v0, v1);
        }
    }
}

template <int CIN, int COUT>
static void conv_launch(cudaStream_t st,
                        const __half* feat, int ldf, const int* nbr,
                        const __half* Wt, const float* sb,
                        const float* resid, int ldr,
                        const float* red, int ldred,
                        float* out, int ldo, __half* outs, int N)
{
    constexpr int SM = SpCfg<CIN, COUT>::SMEM_BYTES;
    cudaFuncSetAttribute(spconv_mma<CIN, COUT>,
                         cudaFuncAttributeMaxDynamicSharedMemorySize, SM);
    const int grid = (N + 127) / 128;
    spconv_mma<CIN, COUT><<<grid, 256, SM, st>>>(
        feat, ldf, nbr, Wt, sb, resid, ldr, red, ldred, out, ldo, outs, N);
}

template <int CIN, int COUT>
static void pack_launch(const float* W, __half* Wt, int layers)
{
    constexpr int per = SpCfg<CIN, COUT>::PACKED_PER_LAYER;
    const int total = layers * per;
    pack_w_kernel<CIN, COUT><<<(total + 255) / 256, 256>>>(W, Wt, layers);
}

extern "C" void kernel_launch(void* const* d_in, const int* in_sizes, int n_in,
                              void* d_out, int out_size)
{
    const float* voxel  = (const float*)d_in[0];
    const float* Win    = (const float*)d_in[1];
    const float* W32    = (const float*)d_in[2];
    const float* W64    = (const float*)d_in[3];
    const float* Wd3    = (const float*)d_in[4];
    const float* W6432  = (const float*)d_in[5];
    const float* W12864 = (const float*)d_in[6];
    const float* bn32   = (const float*)d_in[7];
    const float* bn64   = (const float*)d_in[8];
    const int* nbr1  = (const int*)d_in[9];
    const int* nbr2  = (const int*)d_in[10];
    const int* nbr3  = (const int*)d_in[11];
    const int* nbr4  = (const int*)d_in[12];
    const int* nbrd2 = (const int*)d_in[13];
    const int* nbrd3 = (const int*)d_in[14];
    const int* nbrd4 = (const int*)d_in[15];
    const int* nbri4 = (const int*)d_in[16];
    const int* nbri3 = (const int*)d_in[17];
    const int* nbri2 = (const int*)d_in[18];

    const int N1 = in_sizes[9]  / 27;
    const int N2 = in_sizes[10] / 27;
    const int N3 = in_sizes[11] / 27;
    const int N4 = in_sizes[12] / 27;

    // One-time stream/event setup (host resources, not device memory).
    static cudaStream_t s1 = nullptr;
    static cudaEvent_t evx1, evx2, evx3, evd1, evd2, evd3;
    if (!s1) {
        cudaStreamCreateWithFlags(&s1, cudaStreamNonBlocking);
        cudaEventCreateWithFlags(&evx1, cudaEventDisableTiming);
        cudaEventCreateWithFlags(&evx2, cudaEventDisableTiming);
        cudaEventCreateWithFlags(&evx3, cudaEventDisableTiming);
        cudaEventCreateWithFlags(&evd1, cudaEventDisableTiming);
        cudaEventCreateWithFlags(&evd2, cudaEventDisableTiming);
        cudaEventCreateWithFlags(&evd3, cudaEventDisableTiming);
    }
    const cudaStream_t s0 = 0;   // legacy (captured) stream

    float* pool = nullptr;
    cudaGetSymbolAddress((void**)&pool, g_pool);

    size_t o = 0;   // float units
    auto takeF = [&](size_t n) { size_t r = o; o += (n + 255) & ~(size_t)255; return pool + r; };
    auto takeH = [&](size_t nh) { return (__half*)takeF((nh + 1) / 2); };

    // ---- packed fp16 weights ----
    constexpr int Pin    = SpCfg<4, 32>::PACKED_PER_LAYER;
    constexpr int P32    = SpCfg<32, 32>::PACKED_PER_LAYER;
    constexpr int P64    = SpCfg<64, 64>::PACKED_PER_LAYER;
    constexpr int Pd3    = SpCfg<32, 64>::PACKED_PER_LAYER;
    constexpr int P6432  = SpCfg<64, 32>::PACKED_PER_LAYER;
    constexpr int P12864 = SpCfg<128, 64>::PACKED_PER_LAYER;
    __half* pWin    = takeH(Pin);
    __half* pW32    = takeH((size_t)10 * P32);
    __half* pW64    = takeH((size_t)10 * P64);
    __half* pWd3    = takeH(Pd3);
    __half* pW6432  = takeH((size_t)3 * P6432);
    __half* pW12864 = takeH((size_t)2 * P12864);
    __half* voxs    = takeH((size_t)N1 * 16);

    // ---- feature buffers: fp32 + fp16 shadow ----
    float *A, *X1, *cat1, *C, *Dm, *X2, *cat2, *Fm, *G, *X3, *cat3, *I, *J, *cat4, *T1;
    __half *As, *X1s, *cat1s, *Cs, *Dms, *X2s, *cat2s, *Fms, *Gs, *X3s, *cat3s,
           *Is, *Js, *cat4s, *T1s;
    auto buf2 = [&](size_t n, float*& b, __half*& s) {
        b = takeF(n); s = takeH(n);
    };
    buf2((size_t)N1 * 32, A, As);
    buf2((size_t)N1 * 32, X1, X1s);
    buf2((size_t)N1 * 64, cat1, cat1s);
    buf2((size_t)N1 * 32, T1, T1s);          // dedicated temp for dec1 t-branch
    buf2((size_t)N2 * 32, C, Cs);
    buf2((size_t)N2 * 32, Dm, Dms);
    buf2((size_t)N2 * 32, X2, X2s);
    buf2((size_t)N2 * 64, cat2, cat2s);
    buf2((size_t)N3 * 64, Fm, Fms);
    buf2((size_t)N3 * 64, G, Gs);
    buf2((size_t)N3 * 64, X3, X3s);
    buf2((size_t)N3 * 128, cat3, cat3s);
    buf2((size_t)N4 * 64, I, Is);
    buf2((size_t)N4 * 64, J, Js);
    buf2((size_t)N4 * 128, cat4, cat4s);

    float* outp = (float*)d_out;

    // ---- prologue (main stream) ----
    pack_launch<4, 32>(Win, pWin, 1);
    pack_launch<32, 32>(W32, pW32, 10);
    pack_launch<64, 64>(W64, pW64, 10);
    pack_launch<32, 64>(Wd3, pWd3, 1);
    pack_launch<64, 32>(W6432, pW6432, 3);
    pack_launch<128, 64>(W12864, pW12864, 2);
    cvt_voxel_kernel<<<(N1 * 16 + 255) / 256, 256>>>(voxel, voxs, N1);

    // ---- Encoder (main) ----
    conv_launch<4, 32>(s0, voxs, 16, nbr1, pWin, bn32 + 0 * 64, nullptr, 0, nullptr, 0, nullptr, 32, As, N1);
    conv_launch<32, 32>(s0, As, 32, nbr1, pW32 + 0 * (size_t)P32, bn32 + 1 * 64, nullptr, 0, nullptr, 0, X1, 32, X1s, N1);
    cudaEventRecord(evx1, s0);
    conv_launch<32, 32>(s0, X1s, 32, nbrd2, pW32 + 1 * (size_t)P32, bn32 + 2 * 64, nullptr, 0, nullptr, 0, nullptr, 32, Cs, N2);
    conv_launch<32, 32>(s0, Cs, 32, nbr2, pW32 + 2 * (size_t)P32, bn32 + 3 * 64, nullptr, 0, nullptr, 0, nullptr, 32, Dms, N2);
    conv_launch<32, 32>(s0, Dms, 32, nbr2, pW32 + 3 * (size_t)P32, bn32 + 4 * 64, nullptr, 0, nullptr, 0, X2, 32, X2s, N2);
    cudaEventRecord(evx2, s0);
    conv_launch<32, 64>(s0, X2s, 32, nbrd3, pWd3, bn64 + 0 * 128, nullptr, 0, nullptr, 0, nullptr, 64, Fms, N3);
    conv_launch<64, 64>(s0, Fms, 64, nbr3, pW64 + 0 * (size_t)P64, bn64 + 1 * 128, nullptr, 0, nullptr, 0, nullptr, 64, Gs, N3);
    conv_launch<64, 64>(s0, Gs, 64, nbr3, pW64 + 1 * (size_t)P64, bn64 + 2 * 128, nullptr, 0, nullptr, 0, X3, 64, X3s, N3);
    cudaEventRecord(evx3, s0);

    // ---- Side stream: decoder t-branches (forked off encoder outputs) ----
    cudaStreamWaitEvent(s1, evx1, 0);
    conv_launch<32, 32>(s1, X1s, 32, nbr1, pW32 + 7 * (size_t)P32, bn32 + 8 * 64, nullptr, 0, nullptr, 0, nullptr, 32, T1s, N1);
    conv_launch<32, 32>(s1, T1s, 32, nbr1, pW32 + 8 * (size_t)P32, bn32 + 9 * 64, X1, 32, nullptr, 0, cat1 + 32, 64, cat1s + 32, N1);
    cudaEventRecord(evd1, s1);
    cudaStreamWaitEvent(s1, evx2, 0);
    conv_launch<32, 32>(s1, X2s, 32, nbr2, pW32 + 4 * (size_t)P32, bn32 + 5 * 64, nullptr, 0, nullptr, 0, nullptr, 32, Cs, N2);
    conv_launch<32, 32>(s1, Cs, 32, nbr2, pW32 + 5 * (size_t)P32, bn32 + 6 * 64, X2, 32, nullptr, 0, cat2 + 32, 64, cat2s + 32, N2);
    cudaEventRecord(evd2, s1);
    cudaStreamWaitEvent(s1, evx3, 0);
    conv_launch<64, 64>(s1, X3s, 64, nbr3, pW64 + 8 * (size_t)P64, bn64 + 9 * 128, nullptr, 0, nullptr, 0, nullptr, 64, Fms, N3);
    conv_launch<64, 64>(s1, Fms, 64, nbr3, pW64 + 9 * (size_t)P64, bn64 + 10 * 128, X3, 64, nullptr, 0, cat3 + 64, 128, cat3s + 64, N3);
    cudaEventRecord(evd3, s1);

    // ---- Main: encoder tail + bottleneck ----
    conv_launch<64, 64>(s0, X3s, 64, nbrd4, pW64 + 2 * (size_t)P64, bn64 + 3 * 128, nullptr, 0, nullptr, 0, nullptr, 64, Is, N4);
    conv_launch<64, 64>(s0, Is, 64, nbr4, pW64 + 3 * (size_t)P64, bn64 + 4 * 128, nullptr, 0, nullptr, 0, nullptr, 64, Js, N4);
    conv_launch<64, 64>(s0, Js, 64, nbr4, pW64 + 4 * (size_t)P64, bn64 + 5 * 128, nullptr, 0, nullptr, 0, cat4, 128, cat4s, N4);
    conv_launch<64, 64>(s0, cat4s, 128, nbr4, pW64 + 5 * (size_t)P64, bn64 + 6 * 128, nullptr, 0, nullptr, 0, nullptr, 64, Is, N4);
    conv_launch<64, 64>(s0, Is, 64, nbr4, pW64 + 6 * (size_t)P64, bn64 + 7 * 128, cat4, 128, nullptr, 0, cat4 + 64, 128, cat4s + 64, N4);
    conv_launch<128, 64>(s0, cat4s, 128, nbr4, pW12864 + 0 * (size_t)P12864, bn64 + 11 * 128, nullptr, 0, cat4, 128, nullptr, 64, Js, N4);

    // ---- Decoder level 3 ----
    conv_launch<64, 64>(s0, Js, 64, nbri4, pW64 + 7 * (size_t)P64, bn64 + 8 * 128, nullptr, 0, nullptr, 0, cat3, 128, cat3s, N3);
    cudaStreamWaitEvent(s0, evd3, 0);
    conv_launch<128, 64>(s0, cat3s, 128, nbr3, pW12864 + 1 * (size_t)P12864, bn64 + 12 * 128, nullptr, 0, cat3, 128, nullptr, 64, Gs, N3);

    // ---- Decoder level 2 ----
    conv_launch<64, 32>(s0, Gs, 64, nbri3, pW6432 + 0 * (size_t)P6432, bn32 + 11 * 64, nullptr, 0, nullptr, 0, cat2, 64, cat2s, N2);
    cudaStreamWaitEvent(s0, evd2, 0);
    conv_launch<64, 32>(s0, cat2s, 64, nbr2, pW6432 + 1 * (size_t)P6432, bn32 + 12 * 64, nullptr, 0, cat2, 64, nullptr, 32, Dms, N2);

    // ---- Decoder level 1 ----
    conv_launch<32, 32>(s0, Dms, 32, nbri2, pW32 + 6 * (size_t)P32, bn32 + 7 * 64, nullptr, 0, nullptr, 0, cat1, 64, cat1s, N1);
    cudaStreamWaitEvent(s0, evd1, 0);
    conv_launch<64, 32>(s0, cat1s, 64, nbr1, pW6432 + 2 * (size_t)P6432, bn32 + 13 * 64, nullptr, 0, cat1, 64, nullptr, 32, As, N1);

    // ---- Head ----
    conv_launch<32, 32>(s0, As, 32, nbr1, pW32 + 9 * (size_t)P32, bn32 + 10 * 64, nullptr, 0, nullptr, 0, outp, 32, nullptr, N1);
}